// round 8
// baseline (speedup 1.0000x reference)
#include <cuda_runtime.h>
#include <math.h>
#include <stdint.h>

// ---------------------------------------------------------------------------
// problem constants
// ---------------------------------------------------------------------------
#define BS     16384
#define NC     2000
#define NPADC  2048
#define DIM    512
#define TMR    128              // M rows per CTA
#define NCH    256              // classes per N chunk
#define KSTG   128              // K elements (=bytes, s8) per stage
#define ROWB   144              // padded smem row stride (128B data + 16 pad)
#define ABLK   (128 * ROWB)     // 18432
#define BBLK   (256 * ROWB)     // 36864
#define STG    (ABLK + BBLK)    // 55296
#define NSTG   3
#define DSMEM  (NSTG * STG)     // 165888
#define NITER  32               // 8 n-chunks * 4 k-blocks(128)

// ---------------------------------------------------------------------------
// device scratch (allocation-free)
// ---------------------------------------------------------------------------
__device__ float g_finv[BS];
__device__ float g_winv[NC];
__device__ float g_ta[BS];
__device__ float g_lse[BS];
__device__ float g_corr[BS];
__device__ float g_sa[BS];          // per-row dequant scale (f)
__device__ float g_sb[NPADC];       // per-class dequant scale (w)
__device__ int8_t g_fa[(size_t)BS * DIM];
__device__ int8_t g_wa[(size_t)NPADC * DIM];

// ---------------------------------------------------------------------------
// helpers
// ---------------------------------------------------------------------------
static __device__ __forceinline__ uint32_t sm2u(const void* p) {
    uint32_t a;
    asm("{ .reg .u64 t; cvta.to.shared.u64 t, %1; cvt.u32.u64 %0, t; }"
        : "=r"(a) : "l"(p));
    return a;
}

#define LDSM4(r0, r1, r2, r3, addr) \
    asm volatile("ldmatrix.sync.aligned.m8n8.x4.shared.b16 {%0,%1,%2,%3}, [%4];" \
                 : "=r"(r0), "=r"(r1), "=r"(r2), "=r"(r3) : "r"(addr))

#define IMMA16832(d, a, b) \
    asm volatile("mma.sync.aligned.m16n8k32.row.col.s32.s8.s8.s32 " \
                 "{%0,%1,%2,%3}, {%4,%5,%6,%7}, {%8,%9}, {%0,%1,%2,%3};" \
                 : "+r"((d)[0]), "+r"((d)[1]), "+r"((d)[2]), "+r"((d)[3]) \
                 : "r"((a)[0]), "r"((a)[1]), "r"((a)[2]), "r"((a)[3]), \
                   "r"((b)[0]), "r"((b)[1]))

#define CPASYNC16(dst, src) \
    asm volatile("cp.async.cg.shared.global [%0], [%1], 16;" :: "r"(dst), "l"(src))

// ---------------------------------------------------------------------------
// prep: rownorm + per-row maxabs int8 quant.
// q = rnd(v * 127/maxabs);  dequant scale sa = maxabs * inv_norm / 127
// ---------------------------------------------------------------------------
__global__ void prep_f_kernel(const float* __restrict__ x) {
    int row = blockIdx.x;
    const float4* p = reinterpret_cast<const float4*>(x + (size_t)row * DIM);
    float4 v = p[threadIdx.x];
    float s = v.x * v.x + v.y * v.y + v.z * v.z + v.w * v.w;
    float mx = fmaxf(fmaxf(fabsf(v.x), fabsf(v.y)), fmaxf(fabsf(v.z), fabsf(v.w)));
    #pragma unroll
    for (int o = 16; o > 0; o >>= 1) {
        s  += __shfl_xor_sync(0xffffffffu, s, o);
        mx  = fmaxf(mx, __shfl_xor_sync(0xffffffffu, mx, o));
    }
    __shared__ float sm[4], sx[4];
    __shared__ float sqs;
    int warp = threadIdx.x >> 5;
    if ((threadIdx.x & 31) == 0) { sm[warp] = s; sx[warp] = mx; }
    __syncthreads();
    if (threadIdx.x == 0) {
        float t  = sm[0] + sm[1] + sm[2] + sm[3];
        float m  = fmaxf(fmaxf(sx[0], sx[1]), fmaxf(sx[2], sx[3]));
        float inv = 1.0f / fmaxf(sqrtf(t), 1e-12f);
        g_finv[row] = inv;
        g_sa[row] = m * inv * (1.0f / 127.0f);
        sqs = 127.0f / m;
    }
    __syncthreads();
    float qs = sqs;
    char4 q;
    q.x = (char)__float2int_rn(v.x * qs);
    q.y = (char)__float2int_rn(v.y * qs);
    q.z = (char)__float2int_rn(v.z * qs);
    q.w = (char)__float2int_rn(v.w * qs);
    reinterpret_cast<char4*>(g_fa + (size_t)row * DIM)[threadIdx.x] = q;
}

__global__ void prep_w_kernel(const float* __restrict__ x) {
    int row = blockIdx.x;
    if (row >= NC) {
        char4 z; z.x = z.y = z.z = z.w = 0;
        reinterpret_cast<char4*>(g_wa + (size_t)row * DIM)[threadIdx.x] = z;
        if (threadIdx.x == 0) g_sb[row] = 0.0f;
        return;
    }
    const float4* p = reinterpret_cast<const float4*>(x + (size_t)row * DIM);
    float4 v = p[threadIdx.x];
    float s = v.x * v.x + v.y * v.y + v.z * v.z + v.w * v.w;
    float mx = fmaxf(fmaxf(fabsf(v.x), fabsf(v.y)), fmaxf(fabsf(v.z), fabsf(v.w)));
    #pragma unroll
    for (int o = 16; o > 0; o >>= 1) {
        s  += __shfl_xor_sync(0xffffffffu, s, o);
        mx  = fmaxf(mx, __shfl_xor_sync(0xffffffffu, mx, o));
    }
    __shared__ float sm[4], sx[4];
    __shared__ float sqs;
    int warp = threadIdx.x >> 5;
    if ((threadIdx.x & 31) == 0) { sm[warp] = s; sx[warp] = mx; }
    __syncthreads();
    if (threadIdx.x == 0) {
        float t  = sm[0] + sm[1] + sm[2] + sm[3];
        float m  = fmaxf(fmaxf(sx[0], sx[1]), fmaxf(sx[2], sx[3]));
        float inv = 1.0f / fmaxf(sqrtf(t), 1e-12f);
        g_winv[row] = inv;
        g_sb[row] = m * inv * (1.0f / 127.0f);
        sqs = 127.0f / m;
    }
    __syncthreads();
    float qs = sqs;
    char4 q;
    q.x = (char)__float2int_rn(v.x * qs);
    q.y = (char)__float2int_rn(v.y * qs);
    q.z = (char)__float2int_rn(v.z * qs);
    q.w = (char)__float2int_rn(v.w * qs);
    reinterpret_cast<char4*>(g_wa + (size_t)row * DIM)[threadIdx.x] = q;
}

// ---------------------------------------------------------------------------
// per-row gathers (exact f32): g_ta = -0.95*tgt - 0.01*aux_sum
// ---------------------------------------------------------------------------
__global__ void gather_kernel(const float* __restrict__ f, const float* __restrict__ w,
                              const int* __restrict__ label, const int* __restrict__ aux) {
    int row  = blockIdx.x;
    int warp = threadIdx.x >> 5;
    int lane = threadIdx.x & 31;
    int cls  = (warp == 0) ? label[row] : aux[row * 5 + warp - 1];
    const float4* fr = reinterpret_cast<const float4*>(f + (size_t)row * DIM);
    const float4* wr = reinterpret_cast<const float4*>(w + (size_t)cls * DIM);
    float s = 0.0f;
    #pragma unroll
    for (int k = lane; k < DIM / 4; k += 32) {
        float4 a = fr[k], b = wr[k];
        s += a.x * b.x + a.y * b.y + a.z * b.z + a.w * b.w;
    }
    #pragma unroll
    for (int o = 16; o > 0; o >>= 1) s += __shfl_xor_sync(0xffffffffu, s, o);
    __shared__ float sm[6];
    if (lane == 0) sm[warp] = s * g_finv[row] * g_winv[cls] * 20.0f;
    __syncthreads();
    if (threadIdx.x == 0) {
        float tgt  = sm[0];
        float auxs = sm[1] + sm[2] + sm[3] + sm[4] + sm[5];
        g_ta[row] = -0.95f * tgt - 0.01f * auxs;
    }
}

// ---------------------------------------------------------------------------
// fused INT8 IMMA GEMM + fixed-max softmax reduction.
// CTA tile 128(M) x 256(N), 8 warps = 2(M) x 4(N), warp tile 64x64.
// 3-stage cp.async pipeline of K128 blocks (bytes identical to bf16 version;
// fragment addressing identical -- only the MMA opcode and acc type change).
// ---------------------------------------------------------------------------
__global__ void __launch_bounds__(256, 1)
gemm_fused(const int* __restrict__ label) {
    extern __shared__ char dsm[];
    __shared__ float s_sb[NCH];
    // final-reduction arrays aliased into the (then-dead) pipeline buffer
    float* s_sum = reinterpret_cast<float*>(dsm);            // [4][128]
    float* s_max = reinterpret_cast<float*>(dsm + 2048);     // [4][128]
    int*   s_idx = reinterpret_cast<int*>(dsm + 4096);       // [4][128]

    const int tid   = threadIdx.x;
    const int lane  = tid & 31;
    const int wid   = tid >> 5;
    const int warpM = wid & 1;     // rows warpM*64
    const int warpN = wid >> 1;    // cols warpN*64
    const uint32_t sbase = sm2u(dsm);
    const int mBase = blockIdx.x * TMR;

    // ldmatrix intra-tile offsets (byte-identical to bf16 layout)
    const uint32_t aoff = (uint32_t)(warpM * 64 + (lane & 15)) * ROWB
                        + (uint32_t)(lane >> 4) * 16;
    const uint32_t boff = (uint32_t)(warpN * 64 + (lane & 7) + ((lane >> 4) << 3)) * ROWB
                        + (uint32_t)((lane >> 3) & 1) * 16;

    // per-thread row scales: rows warpM*64 + mt*16 + rh*8 + (lane>>2)
    float ksa[4][2];
    #pragma unroll
    for (int mt = 0; mt < 4; ++mt)
        #pragma unroll
        for (int rh = 0; rh < 2; ++rh)
            ksa[mt][rh] = 28.853900817779268f *
                g_sa[mBase + warpM * 64 + mt * 16 + rh * 8 + (lane >> 2)];

    int   acc[4][8][4];            // [mt][n8][j] s32
    float vsum[4][2];
    float vmax[4][2];
    int   vidx[4][2];
    #pragma unroll
    for (int mt = 0; mt < 4; ++mt)
        #pragma unroll
        for (int rh = 0; rh < 2; ++rh) {
            vsum[mt][rh] = 0.0f; vmax[mt][rh] = -1e30f; vidx[mt][rh] = -1;
        }

    // ---- stage loader: A(128x128B) + B(256x128B), one commit group ----
    auto load_stage = [&](int t, int slot) {
        const int nc = t >> 2, kb = t & 3;
        const uint32_t sb = sbase + (uint32_t)slot * STG;
        const int8_t* Asrc = g_fa + (size_t)mBase * DIM + kb * KSTG;
        const int8_t* Bsrc = g_wa + (size_t)(nc * NCH) * DIM + kb * KSTG;
        #pragma unroll
        for (int i = 0; i < 4; ++i) {          // A: 1024 16B chunks
            int ch = tid + 256 * i;
            int row = ch >> 3, c8 = ch & 7;
            CPASYNC16(sb + (uint32_t)row * ROWB + c8 * 16,
                      Asrc + (size_t)row * DIM + c8 * 16);
        }
        #pragma unroll
        for (int i = 0; i < 8; ++i) {          // B: 2048 16B chunks
            int ch = tid + 256 * i;
            int row = ch >> 3, c8 = ch & 7;
            CPASYNC16(sb + ABLK + (uint32_t)row * ROWB + c8 * 16,
                      Bsrc + (size_t)row * DIM + c8 * 16);
        }
        asm volatile("cp.async.commit_group;" ::: "memory");
    };

    load_stage(0, 0);
    load_stage(1, 1);

    int csSlot = 0, ldSlot = 2;
    for (int t = 0; t < NITER; ++t) {
        if (t + 1 < NITER) {
            asm volatile("cp.async.wait_group 1;" ::: "memory");
        } else {
            asm volatile("cp.async.wait_group 0;" ::: "memory");
        }
        __syncthreads();
        if (t + 2 < NITER) {
            load_stage(t + 2, ldSlot);
            if (++ldSlot == NSTG) ldSlot = 0;
        }

        if ((t & 3) == 0) {
            // stage class scales for this n-chunk + zero accumulators
            s_sb[tid] = g_sb[(t >> 2) * NCH + tid];
            #pragma unroll
            for (int mt = 0; mt < 4; ++mt)
                #pragma unroll
                for (int n8 = 0; n8 < 8; ++n8)
                    #pragma unroll
                    for (int j = 0; j < 4; ++j) acc[mt][n8][j] = 0;
        }

        const uint32_t sb = sbase + (uint32_t)csSlot * STG;
        if (++csSlot == NSTG) csSlot = 0;
        const uint32_t aS = sb + aoff;
        const uint32_t bS = sb + ABLK + boff;
        #pragma unroll
        for (int kk = 0; kk < 4; ++kk) {       // 4 x K32 slices (32B each)
            uint32_t Af[4][4];
            #pragma unroll
            for (int mt = 0; mt < 4; ++mt)
                LDSM4(Af[mt][0], Af[mt][1], Af[mt][2], Af[mt][3],
                      aS + (uint32_t)mt * 16 * ROWB + kk * 32);
            uint32_t Bf[8][2];
            #pragma unroll
            for (int nt = 0; nt < 4; ++nt) {
                uint32_t r0, r1, r2, r3;
                LDSM4(r0, r1, r2, r3, bS + (uint32_t)nt * 16 * ROWB + kk * 32);
                Bf[2 * nt][0] = r0;     Bf[2 * nt][1] = r1;
                Bf[2 * nt + 1][0] = r2; Bf[2 * nt + 1][1] = r3;
            }
            #pragma unroll
            for (int mt = 0; mt < 4; ++mt)
                #pragma unroll
                for (int n8 = 0; n8 < 8; ++n8)
                    IMMA16832(acc[mt][n8], Af[mt], Bf[n8]);
        }

        if ((t & 3) == 3) {
            // epilogue: dequant, exp(20c - 20), argmax, mask padding
            const int ncBase = (t >> 2) * NCH + warpN * 64;
            #pragma unroll
            for (int n8 = 0; n8 < 8; ++n8) {
                const int c0 = warpN * 64 + n8 * 8 + (lane & 3) * 2;
                const float sb0 = s_sb[c0];
                const float sb1 = s_sb[c0 + 1];
                const int cls0 = ncBase + n8 * 8 + (lane & 3) * 2;
                #pragma unroll
                for (int mt = 0; mt < 4; ++mt) {
                    #pragma unroll
                    for (int j = 0; j < 4; ++j) {
                        int cls = cls0 + (j & 1);
                        if (cls < NC) {
                            int   rh = j >> 1;
                            float vf = __int2float_rn(acc[mt][n8][j]);
                            float vc = vf * ((j & 1) ? sb1 : sb0);   // cos / sa
                            if (vc > vmax[mt][rh]) { vmax[mt][rh] = vc; vidx[mt][rh] = cls; }
                            // exp(20cos - 20) = 2^(vc*ksa - 28.8539)
                            float tt = fmaf(vc, ksa[mt][rh], -28.853900817779268f);
                            float fj = tt + 12582912.0f;      // rn-to-int magic
                            float fi = fj - 12582912.0f;
                            float rr = tt - fi;               // [-0.5, 0.5]
                            int   ei = __float_as_int(fj);
                            int   sb2 = (ei + (127 - 0x4B400000)) << 23;  // 2^n bits
                            float q  = fmaf(rr, 0.0096181291f, 0.055504109f);
                            q = fmaf(rr, q, 0.24022651f);
                            q = fmaf(rr, q, 0.69314718f);
                            q = fmaf(rr, q, 1.0f);
                            vsum[mt][rh] = fmaf(q, __int_as_float(sb2), vsum[mt][rh]);
                        }
                    }
                }
            }
        }
    }
    __syncthreads();   // pipeline buffer dead; reuse for reduction

    // reduce across quad lanes (cols within warp), write per-N-warp partials
    #pragma unroll
    for (int mt = 0; mt < 4; ++mt) {
        #pragma unroll
        for (int rh = 0; rh < 2; ++rh) {
            float s = vsum[mt][rh], m = vmax[mt][rh];
            int   ix = vidx[mt][rh];
            #pragma unroll
            for (int o = 1; o <= 2; o <<= 1) {
                float so = __shfl_xor_sync(0xffffffffu, s, o);
                float mo = __shfl_xor_sync(0xffffffffu, m, o);
                int   io = __shfl_xor_sync(0xffffffffu, ix, o);
                s += so;
                if (mo > m) { m = mo; ix = io; }
            }
            if ((lane & 3) == 0) {
                int row = warpM * 64 + mt * 16 + rh * 8 + (lane >> 2);
                s_sum[warpN * TMR + row] = s;
                s_max[warpN * TMR + row] = m;
                s_idx[warpN * TMR + row] = ix;
            }
        }
    }
    __syncthreads();

    if (tid < TMR) {
        float sum = 0.0f, m = -1e30f;
        int   ix = -1;
        #pragma unroll
        for (int wn = 0; wn < 4; ++wn) {
            sum += s_sum[wn * TMR + tid];
            float mw = s_max[wn * TMR + tid];
            if (mw > m) { m = mw; ix = s_idx[wn * TMR + tid]; }
        }
        int grow = mBase + tid;
        g_lse[grow]  = 20.0f + __logf(sum);
        g_corr[grow] = (ix == label[grow]) ? 1.0f : 0.0f;
    }
}

// ---------------------------------------------------------------------------
// final deterministic reduction
// ---------------------------------------------------------------------------
__global__ void final_kernel(float* __restrict__ out, int out_size) {
    int tid = threadIdx.x;
    float sl = 0.0f, sc = 0.0f;
    for (int i = tid; i < BS; i += 1024) {
        sl += g_lse[i] + g_ta[i];
        sc += g_corr[i];
    }
    #pragma unroll
    for (int o = 16; o > 0; o >>= 1) {
        sl += __shfl_xor_sync(0xffffffffu, sl, o);
        sc += __shfl_xor_sync(0xffffffffu, sc, o);
    }
    __shared__ float a1[32], a2[32];
    int w = tid >> 5, l = tid & 31;
    if (l == 0) { a1[w] = sl; a2[w] = sc; }
    __syncthreads();
    if (w == 0) {
        sl = a1[l];
        sc = a2[l];
        #pragma unroll
        for (int o = 16; o > 0; o >>= 1) {
            sl += __shfl_xor_sync(0xffffffffu, sl, o);
            sc += __shfl_xor_sync(0xffffffffu, sc, o);
        }
        if (tid == 0) {
            out[0] = sl * (1.0f / BS);
            if (out_size > 1) out[1] = sc * (1.0f / BS);
        }
    }
}

// ---------------------------------------------------------------------------
// host
// ---------------------------------------------------------------------------
extern "C" void kernel_launch(void* const* d_in, const int* in_sizes, int n_in,
                              void* d_out, int out_size) {
    const float* f     = (const float*)d_in[0];
    const float* w     = (const float*)d_in[1];
    const int*   label = (const int*)d_in[2];
    const int*   aux   = (const int*)d_in[3];
    (void)in_sizes; (void)n_in;

    static int configured = 0;
    if (!configured) {
        cudaFuncSetAttribute(gemm_fused,
                             cudaFuncAttributeMaxDynamicSharedMemorySize, DSMEM);
        configured = 1;
    }

    prep_f_kernel<<<BS, 128>>>(f);
    prep_w_kernel<<<NPADC, 128>>>(w);
    gather_kernel<<<BS, 192>>>(f, w, label, aux);
    gemm_fused<<<BS / TMR, 256, DSMEM>>>(label);
    final_kernel<<<1, 1024>>>((float*)d_out, out_size);
}

// round 9
// speedup vs baseline: 1.9915x; 1.9915x over previous
#include <cuda_runtime.h>
#include <cuda_bf16.h>
#include <math.h>
#include <stdint.h>

// ---------------------------------------------------------------------------
// problem constants
// ---------------------------------------------------------------------------
#define BS     16384
#define NC     2000
#define NPADC  2048
#define DIM    512
#define TMR    128              // M rows per CTA
#define NCH    256              // classes per N chunk
#define BK     64               // K per stage
#define ROWB   144              // padded smem row stride (72 bf16)
#define ABLK   (128 * ROWB)     // 18432
#define BBLK   (256 * ROWB)     // 36864
#define STG    (ABLK + BBLK)    // 55296
#define NSTG   3
#define DSMEM  (NSTG * STG)     // 165888
#define NITER  64               // 8 n-chunks * 8 k-blocks

// ---------------------------------------------------------------------------
// device scratch (allocation-free)
// ---------------------------------------------------------------------------
__device__ float g_ta[BS];
__device__ float g_lse[BS];
__device__ float g_corr[BS];
__device__ __nv_bfloat16 g_fb[(size_t)BS * DIM];
__device__ __nv_bfloat16 g_wb[(size_t)NPADC * DIM];

// ---------------------------------------------------------------------------
// helpers
// ---------------------------------------------------------------------------
static __device__ __forceinline__ uint32_t sm2u(const void* p) {
    uint32_t a;
    asm("{ .reg .u64 t; cvta.to.shared.u64 t, %1; cvt.u32.u64 %0, t; }"
        : "=r"(a) : "l"(p));
    return a;
}

#define LDSM4(r0, r1, r2, r3, addr) \
    asm volatile("ldmatrix.sync.aligned.m8n8.x4.shared.b16 {%0,%1,%2,%3}, [%4];" \
                 : "=r"(r0), "=r"(r1), "=r"(r2), "=r"(r3) : "r"(addr))

#define MMA16816(d, a, b) \
    asm volatile("mma.sync.aligned.m16n8k16.row.col.f32.bf16.bf16.f32 " \
                 "{%0,%1,%2,%3}, {%4,%5,%6,%7}, {%8,%9}, {%0,%1,%2,%3};" \
                 : "+f"((d)[0]), "+f"((d)[1]), "+f"((d)[2]), "+f"((d)[3]) \
                 : "r"((a)[0]), "r"((a)[1]), "r"((a)[2]), "r"((a)[3]), \
                   "r"((b)[0]), "r"((b)[1]))

#define CPASYNC16(dst, src) \
    asm volatile("cp.async.cg.shared.global [%0], [%1], 16;" :: "r"(dst), "l"(src))

// ---------------------------------------------------------------------------
// prep: warp-per-row rownorm + bf16 convert (no block barriers).
// ---------------------------------------------------------------------------
__global__ void prep_f_kernel(const float* __restrict__ x) {
    int warp = threadIdx.x >> 5;
    int lane = threadIdx.x & 31;
    int row  = blockIdx.x * 8 + warp;
    const float4* p = reinterpret_cast<const float4*>(x + (size_t)row * DIM);
    float4 v[4];
    float s = 0.0f;
    #pragma unroll
    for (int k = 0; k < 4; ++k) {
        v[k] = p[lane + 32 * k];
        s += v[k].x * v[k].x + v[k].y * v[k].y + v[k].z * v[k].z + v[k].w * v[k].w;
    }
    #pragma unroll
    for (int o = 16; o > 0; o >>= 1) s += __shfl_xor_sync(0xffffffffu, s, o);
    float inv = 1.0f / fmaxf(sqrtf(s), 1e-12f);
    uint2* dp = reinterpret_cast<uint2*>(g_fb + (size_t)row * DIM);
    #pragma unroll
    for (int k = 0; k < 4; ++k) {
        __nv_bfloat162 h0 = __floats2bfloat162_rn(v[k].x * inv, v[k].y * inv);
        __nv_bfloat162 h1 = __floats2bfloat162_rn(v[k].z * inv, v[k].w * inv);
        uint2 u;
        u.x = *reinterpret_cast<uint32_t*>(&h0);
        u.y = *reinterpret_cast<uint32_t*>(&h1);
        dp[lane + 32 * k] = u;
    }
}

__global__ void prep_w_kernel(const float* __restrict__ x) {
    int warp = threadIdx.x >> 5;
    int lane = threadIdx.x & 31;
    int row  = blockIdx.x * 8 + warp;
    uint2* dp = reinterpret_cast<uint2*>(g_wb + (size_t)row * DIM);
    if (row >= NC) {
        uint2 z; z.x = 0u; z.y = 0u;
        #pragma unroll
        for (int k = 0; k < 4; ++k) dp[lane + 32 * k] = z;
        return;
    }
    const float4* p = reinterpret_cast<const float4*>(x + (size_t)row * DIM);
    float4 v[4];
    float s = 0.0f;
    #pragma unroll
    for (int k = 0; k < 4; ++k) {
        v[k] = p[lane + 32 * k];
        s += v[k].x * v[k].x + v[k].y * v[k].y + v[k].z * v[k].z + v[k].w * v[k].w;
    }
    #pragma unroll
    for (int o = 16; o > 0; o >>= 1) s += __shfl_xor_sync(0xffffffffu, s, o);
    float inv = 1.0f / fmaxf(sqrtf(s), 1e-12f);
    #pragma unroll
    for (int k = 0; k < 4; ++k) {
        __nv_bfloat162 h0 = __floats2bfloat162_rn(v[k].x * inv, v[k].y * inv);
        __nv_bfloat162 h1 = __floats2bfloat162_rn(v[k].z * inv, v[k].w * inv);
        uint2 u;
        u.x = *reinterpret_cast<uint32_t*>(&h0);
        u.y = *reinterpret_cast<uint32_t*>(&h1);
        dp[lane + 32 * k] = u;
    }
}

// ---------------------------------------------------------------------------
// per-row gathers from bf16 normalized arrays:
// g_ta = -0.95*tgt - 0.01*aux_sum   (logits = 20 * cosine)
// f row staged in smem once; 6 warps do one dot each.
// ---------------------------------------------------------------------------
__global__ void gather_kernel(const int* __restrict__ label, const int* __restrict__ aux) {
    __shared__ uint32_t s_f[DIM / 2];     // 256 bf162 pairs
    __shared__ float sm[6];
    int row  = blockIdx.x;
    int tid  = threadIdx.x;               // 192 threads
    int warp = tid >> 5;
    int lane = tid & 31;

    const uint32_t* fr = reinterpret_cast<const uint32_t*>(g_fb + (size_t)row * DIM);
    s_f[tid] = fr[tid];
    if (tid < 64) s_f[192 + tid] = fr[192 + tid];
    __syncthreads();

    int cls = (warp == 0) ? label[row] : aux[row * 5 + warp - 1];
    const uint32_t* wr = reinterpret_cast<const uint32_t*>(g_wb + (size_t)cls * DIM);
    float s = 0.0f;
    #pragma unroll
    for (int k = 0; k < 8; ++k) {
        uint32_t fp = s_f[lane + 32 * k];
        uint32_t wp = wr[lane + 32 * k];
        float2 fa = __bfloat1622float2(*reinterpret_cast<__nv_bfloat162*>(&fp));
        float2 wa = __bfloat1622float2(*reinterpret_cast<__nv_bfloat162*>(&wp));
        s = fmaf(fa.x, wa.x, s);
        s = fmaf(fa.y, wa.y, s);
    }
    #pragma unroll
    for (int o = 16; o > 0; o >>= 1) s += __shfl_xor_sync(0xffffffffu, s, o);
    if (lane == 0) sm[warp] = s * 20.0f;
    __syncthreads();
    if (tid == 0) {
        float tgt  = sm[0];
        float auxs = sm[1] + sm[2] + sm[3] + sm[4] + sm[5];
        g_ta[row] = -0.95f * tgt - 0.01f * auxs;
    }
}

// ---------------------------------------------------------------------------
// fused bf16 mma.sync GEMM + fixed-max softmax reduction.  (R7 state)
// CTA tile 128(M) x 256(N), 8 warps = 2(M) x 4(N), warp tile 64x64.
// 3-stage cp.async pipeline of K64 blocks.
// ---------------------------------------------------------------------------
__global__ void __launch_bounds__(256, 1)
gemm_fused(const int* __restrict__ label) {
    extern __shared__ char dsm[];
    // final-reduction arrays aliased into the (then-dead) pipeline buffer
    float* s_sum = reinterpret_cast<float*>(dsm);            // [4][128]
    float* s_max = reinterpret_cast<float*>(dsm + 2048);     // [4][128]
    int*   s_idx = reinterpret_cast<int*>(dsm + 4096);       // [4][128]

    const int tid   = threadIdx.x;
    const int lane  = tid & 31;
    const int wid   = tid >> 5;
    const int warpM = wid & 1;     // rows warpM*64
    const int warpN = wid >> 1;    // cols warpN*64
    const uint32_t sbase = sm2u(dsm);
    const int mBase = blockIdx.x * TMR;

    // ldmatrix intra-tile offsets
    const uint32_t aoff = (uint32_t)(warpM * 64 + (lane & 15)) * ROWB
                        + (uint32_t)(lane >> 4) * 16;
    const uint32_t boff = (uint32_t)(warpN * 64 + (lane & 7) + ((lane >> 4) << 3)) * ROWB
                        + (uint32_t)((lane >> 3) & 1) * 16;

    float acc[4][8][4];            // [mt][n8][j]
    float vsum[4][2];
    float vmax[4][2];
    int   vidx[4][2];
    #pragma unroll
    for (int mt = 0; mt < 4; ++mt)
        #pragma unroll
        for (int rh = 0; rh < 2; ++rh) {
            vsum[mt][rh] = 0.0f; vmax[mt][rh] = -1e30f; vidx[mt][rh] = -1;
        }

    // ---- stage loader: A(128x64) + B(256x64), one commit group ----
    auto load_stage = [&](int t, int slot) {
        const int nc = t >> 3, kb = t & 7;
        const uint32_t sb = sbase + (uint32_t)slot * STG;
        const __nv_bfloat16* Asrc = g_fb + (size_t)mBase * DIM + kb * BK;
        const __nv_bfloat16* Bsrc = g_wb + (size_t)(nc * NCH) * DIM + kb * BK;
        #pragma unroll
        for (int i = 0; i < 4; ++i) {          // A: 1024 chunks
            int ch = tid + 256 * i;
            int row = ch >> 3, c8 = ch & 7;
            CPASYNC16(sb + (uint32_t)row * ROWB + c8 * 16,
                      Asrc + (size_t)row * DIM + c8 * 8);
        }
        #pragma unroll
        for (int i = 0; i < 8; ++i) {          // B: 2048 chunks
            int ch = tid + 256 * i;
            int row = ch >> 3, c8 = ch & 7;
            CPASYNC16(sb + ABLK + (uint32_t)row * ROWB + c8 * 16,
                      Bsrc + (size_t)row * DIM + c8 * 8);
        }
        asm volatile("cp.async.commit_group;" ::: "memory");
    };

    load_stage(0, 0);
    load_stage(1, 1);

    int csSlot = 0, ldSlot = 2;
    for (int t = 0; t < NITER; ++t) {
        if (t + 1 < NITER) {
            asm volatile("cp.async.wait_group 1;" ::: "memory");
        } else {
            asm volatile("cp.async.wait_group 0;" ::: "memory");
        }
        __syncthreads();
        if (t + 2 < NITER) {
            load_stage(t + 2, ldSlot);
            if (++ldSlot == NSTG) ldSlot = 0;
        }

        if ((t & 7) == 0) {
            #pragma unroll
            for (int mt = 0; mt < 4; ++mt)
                #pragma unroll
                for (int n8 = 0; n8 < 8; ++n8)
                    #pragma unroll
                    for (int j = 0; j < 4; ++j) acc[mt][n8][j] = 0.0f;
        }

        const uint32_t sb = sbase + (uint32_t)csSlot * STG;
        if (++csSlot == NSTG) csSlot = 0;
        const uint32_t aS = sb + aoff;
        const uint32_t bS = sb + ABLK + boff;
        #pragma unroll
        for (int kk = 0; kk < 4; ++kk) {
            uint32_t Af[4][4];
            #pragma unroll
            for (int mt = 0; mt < 4; ++mt)
                LDSM4(Af[mt][0], Af[mt][1], Af[mt][2], Af[mt][3],
                      aS + (uint32_t)mt * 16 * ROWB + kk * 32);
            uint32_t Bf[8][2];
            #pragma unroll
            for (int nt = 0; nt < 4; ++nt) {
                uint32_t r0, r1, r2, r3;
                LDSM4(r0, r1, r2, r3, bS + (uint32_t)nt * 16 * ROWB + kk * 32);
                Bf[2 * nt][0] = r0;     Bf[2 * nt][1] = r1;
                Bf[2 * nt + 1][0] = r2; Bf[2 * nt + 1][1] = r3;
            }
            #pragma unroll
            for (int mt = 0; mt < 4; ++mt)
                #pragma unroll
                for (int n8 = 0; n8 < 8; ++n8)
                    MMA16816(acc[mt][n8], Af[mt], Bf[n8]);
        }

        if ((t & 7) == 7) {
            // epilogue for this n-chunk: exp(20c - 20), argmax, mask padding
            const int ncBase = (t >> 3) * NCH + warpN * 64;
            #pragma unroll
            for (int mt = 0; mt < 4; ++mt) {
                #pragma unroll
                for (int n8 = 0; n8 < 8; ++n8) {
                    #pragma unroll
                    for (int j = 0; j < 4; ++j) {
                        int cls = ncBase + n8 * 8 + (lane & 3) * 2 + (j & 1);
                        if (cls < NC) {
                            float v  = acc[mt][n8][j];       // cosine
                            int   rh = j >> 1;
                            if (v > vmax[mt][rh]) { vmax[mt][rh] = v; vidx[mt][rh] = cls; }
                            // exp(20v - 20) = 2^(28.8539*(v-1)); fixed max = 20
                            float tt = fmaf(v, 28.853900817779268f, -28.853900817779268f);
                            float fj = tt + 12582912.0f;      // rn-to-int magic
                            float fi = fj - 12582912.0f;
                            float rr = tt - fi;               // [-0.5, 0.5]
                            int   ei = __float_as_int(fj);
                            int   sb2 = (ei + (127 - 0x4B400000)) << 23;  // 2^n bits
                            float q  = fmaf(rr, 0.0096181291f, 0.055504109f);
                            q = fmaf(rr, q, 0.24022651f);
                            q = fmaf(rr, q, 0.69314718f);
                            q = fmaf(rr, q, 1.0f);
                            vsum[mt][rh] = fmaf(q, __int_as_float(sb2), vsum[mt][rh]);
                        }
                    }
                }
            }
        }
    }
    __syncthreads();   // pipeline buffer dead; reuse for reduction

    // reduce across quad lanes (cols within warp), write per-N-warp partials
    #pragma unroll
    for (int mt = 0; mt < 4; ++mt) {
        #pragma unroll
        for (int rh = 0; rh < 2; ++rh) {
            float s = vsum[mt][rh], m = vmax[mt][rh];
            int   ix = vidx[mt][rh];
            #pragma unroll
            for (int o = 1; o <= 2; o <<= 1) {
                float so = __shfl_xor_sync(0xffffffffu, s, o);
                float mo = __shfl_xor_sync(0xffffffffu, m, o);
                int   io = __shfl_xor_sync(0xffffffffu, ix, o);
                s += so;
                if (mo > m) { m = mo; ix = io; }
            }
            if ((lane & 3) == 0) {
                int row = warpM * 64 + mt * 16 + rh * 8 + (lane >> 2);
                s_sum[warpN * TMR + row] = s;
                s_max[warpN * TMR + row] = m;
                s_idx[warpN * TMR + row] = ix;
            }
        }
    }
    __syncthreads();

    if (tid < TMR) {
        float sum = 0.0f, m = -1e30f;
        int   ix = -1;
        #pragma unroll
        for (int wn = 0; wn < 4; ++wn) {
            sum += s_sum[wn * TMR + tid];
            float mw = s_max[wn * TMR + tid];
            if (mw > m) { m = mw; ix = s_idx[wn * TMR + tid]; }
        }
        int grow = mBase + tid;
        g_lse[grow]  = 20.0f + __logf(sum);
        g_corr[grow] = (ix == label[grow]) ? 1.0f : 0.0f;
    }
}

// ---------------------------------------------------------------------------
// final deterministic reduction
// ---------------------------------------------------------------------------
__global__ void final_kernel(float* __restrict__ out, int out_size) {
    int tid = threadIdx.x;
    float sl = 0.0f, sc = 0.0f;
    for (int i = tid; i < BS; i += 1024) {
        sl += g_lse[i] + g_ta[i];
        sc += g_corr[i];
    }
    #pragma unroll
    for (int o = 16; o > 0; o >>= 1) {
        sl += __shfl_xor_sync(0xffffffffu, sl, o);
        sc += __shfl_xor_sync(0xffffffffu, sc, o);
    }
    __shared__ float a1[32], a2[32];
    int w = tid >> 5, l = tid & 31;
    if (l == 0) { a1[w] = sl; a2[w] = sc; }
    __syncthreads();
    if (w == 0) {
        sl = a1[l];
        sc = a2[l];
        #pragma unroll
        for (int o = 16; o > 0; o >>= 1) {
            sl += __shfl_xor_sync(0xffffffffu, sl, o);
            sc += __shfl_xor_sync(0xffffffffu, sc, o);
        }
        if (tid == 0) {
            out[0] = sl * (1.0f / BS);
            if (out_size > 1) out[1] = sc * (1.0f / BS);
        }
    }
}

// ---------------------------------------------------------------------------
// host
// ---------------------------------------------------------------------------
extern "C" void kernel_launch(void* const* d_in, const int* in_sizes, int n_in,
                              void* d_out, int out_size) {
    const float* f     = (const float*)d_in[0];
    const float* w     = (const float*)d_in[1];
    const int*   label = (const int*)d_in[2];
    const int*   aux   = (const int*)d_in[3];
    (void)in_sizes; (void)n_in;

    static int configured = 0;
    if (!configured) {
        cudaFuncSetAttribute(gemm_fused,
                             cudaFuncAttributeMaxDynamicSharedMemorySize, DSMEM);
        configured = 1;
    }

    prep_f_kernel<<<BS / 8, 256>>>(f);
    prep_w_kernel<<<NPADC / 8, 256>>>(w);
    gather_kernel<<<BS, 192>>>(label, aux);
    gemm_fused<<<BS / TMR, 256, DSMEM>>>(label);
    final_kernel<<<1, 1024>>>((float*)d_out, out_size);
}

// round 10
// speedup vs baseline: 2.0171x; 1.0129x over previous
#include <cuda_runtime.h>
#include <cuda_bf16.h>
#include <math.h>
#include <stdint.h>

// ---------------------------------------------------------------------------
// problem constants
// ---------------------------------------------------------------------------
#define BS     16384
#define NC     2000
#define NPADC  2048
#define DIM    512
#define TMR    128              // M rows per tile
#define NCH    256              // classes per N chunk
#define BK     64               // K per stage
#define ROWB   144              // padded smem row stride (72 bf16)
#define ABLK   (128 * ROWB)     // 18432
#define BBLK   (256 * ROWB)     // 36864
#define STG    (ABLK + BBLK)    // 55296
#define NSTG   3
#define DSMEM  (NSTG * STG)     // 165888
#define GRID   148              // persistent CTAs (one per SM)
#define NUNITS 1024             // 128 m-tiles * 8 n-chunks
#define NSLOT  32               // 8 n-chunks * 4 warpN partials per row

// ---------------------------------------------------------------------------
// device scratch (allocation-free)
// ---------------------------------------------------------------------------
__device__ float g_ta[BS];
__device__ float g_lse[BS];
__device__ float g_corr[BS];
__device__ float g_psum[NSLOT * BS];    // [slot][row] partial exp-sums
__device__ float g_pmax[NSLOT * BS];    // [slot][row] partial maxima
__device__ int   g_pidx[NSLOT * BS];    // [slot][row] partial argmax
__device__ __nv_bfloat16 g_fb[(size_t)BS * DIM];
__device__ __nv_bfloat16 g_wb[(size_t)NPADC * DIM];

// ---------------------------------------------------------------------------
// helpers
// ---------------------------------------------------------------------------
static __device__ __forceinline__ uint32_t sm2u(const void* p) {
    uint32_t a;
    asm("{ .reg .u64 t; cvta.to.shared.u64 t, %1; cvt.u32.u64 %0, t; }"
        : "=r"(a) : "l"(p));
    return a;
}

#define LDSM4(r0, r1, r2, r3, addr) \
    asm volatile("ldmatrix.sync.aligned.m8n8.x4.shared.b16 {%0,%1,%2,%3}, [%4];" \
                 : "=r"(r0), "=r"(r1), "=r"(r2), "=r"(r3) : "r"(addr))

#define MMA16816(d, a, b) \
    asm volatile("mma.sync.aligned.m16n8k16.row.col.f32.bf16.bf16.f32 " \
                 "{%0,%1,%2,%3}, {%4,%5,%6,%7}, {%8,%9}, {%0,%1,%2,%3};" \
                 : "+f"((d)[0]), "+f"((d)[1]), "+f"((d)[2]), "+f"((d)[3]) \
                 : "r"((a)[0]), "r"((a)[1]), "r"((a)[2]), "r"((a)[3]), \
                   "r"((b)[0]), "r"((b)[1]))

#define CPASYNC16(dst, src) \
    asm volatile("cp.async.cg.shared.global [%0], [%1], 16;" :: "r"(dst), "l"(src))

// ---------------------------------------------------------------------------
// prep: warp-per-row rownorm + bf16 convert (no block barriers).
// ---------------------------------------------------------------------------
__global__ void prep_f_kernel(const float* __restrict__ x) {
    int warp = threadIdx.x >> 5;
    int lane = threadIdx.x & 31;
    int row  = blockIdx.x * 8 + warp;
    const float4* p = reinterpret_cast<const float4*>(x + (size_t)row * DIM);
    float4 v[4];
    float s = 0.0f;
    #pragma unroll
    for (int k = 0; k < 4; ++k) {
        v[k] = p[lane + 32 * k];
        s += v[k].x * v[k].x + v[k].y * v[k].y + v[k].z * v[k].z + v[k].w * v[k].w;
    }
    #pragma unroll
    for (int o = 16; o > 0; o >>= 1) s += __shfl_xor_sync(0xffffffffu, s, o);
    float inv = 1.0f / fmaxf(sqrtf(s), 1e-12f);
    uint2* dp = reinterpret_cast<uint2*>(g_fb + (size_t)row * DIM);
    #pragma unroll
    for (int k = 0; k < 4; ++k) {
        __nv_bfloat162 h0 = __floats2bfloat162_rn(v[k].x * inv, v[k].y * inv);
        __nv_bfloat162 h1 = __floats2bfloat162_rn(v[k].z * inv, v[k].w * inv);
        uint2 u;
        u.x = *reinterpret_cast<uint32_t*>(&h0);
        u.y = *reinterpret_cast<uint32_t*>(&h1);
        dp[lane + 32 * k] = u;
    }
}

__global__ void prep_w_kernel(const float* __restrict__ x) {
    int warp = threadIdx.x >> 5;
    int lane = threadIdx.x & 31;
    int row  = blockIdx.x * 8 + warp;
    uint2* dp = reinterpret_cast<uint2*>(g_wb + (size_t)row * DIM);
    if (row >= NC) {
        uint2 z; z.x = 0u; z.y = 0u;
        #pragma unroll
        for (int k = 0; k < 4; ++k) dp[lane + 32 * k] = z;
        return;
    }
    const float4* p = reinterpret_cast<const float4*>(x + (size_t)row * DIM);
    float4 v[4];
    float s = 0.0f;
    #pragma unroll
    for (int k = 0; k < 4; ++k) {
        v[k] = p[lane + 32 * k];
        s += v[k].x * v[k].x + v[k].y * v[k].y + v[k].z * v[k].z + v[k].w * v[k].w;
    }
    #pragma unroll
    for (int o = 16; o > 0; o >>= 1) s += __shfl_xor_sync(0xffffffffu, s, o);
    float inv = 1.0f / fmaxf(sqrtf(s), 1e-12f);
    #pragma unroll
    for (int k = 0; k < 4; ++k) {
        __nv_bfloat162 h0 = __floats2bfloat162_rn(v[k].x * inv, v[k].y * inv);
        __nv_bfloat162 h1 = __floats2bfloat162_rn(v[k].z * inv, v[k].w * inv);
        uint2 u;
        u.x = *reinterpret_cast<uint32_t*>(&h0);
        u.y = *reinterpret_cast<uint32_t*>(&h1);
        dp[lane + 32 * k] = u;
    }
}

// ---------------------------------------------------------------------------
// per-row gathers from bf16 normalized arrays:
// g_ta = -0.95*tgt - 0.01*aux_sum   (logits = 20 * cosine)
// ---------------------------------------------------------------------------
__global__ void gather_kernel(const int* __restrict__ label, const int* __restrict__ aux) {
    __shared__ uint32_t s_f[DIM / 2];     // 256 bf162 pairs
    __shared__ float sm[6];
    int row  = blockIdx.x;
    int tid  = threadIdx.x;               // 192 threads
    int warp = tid >> 5;
    int lane = tid & 31;

    const uint32_t* fr = reinterpret_cast<const uint32_t*>(g_fb + (size_t)row * DIM);
    s_f[tid] = fr[tid];
    if (tid < 64) s_f[192 + tid] = fr[192 + tid];
    __syncthreads();

    int cls = (warp == 0) ? label[row] : aux[row * 5 + warp - 1];
    const uint32_t* wr = reinterpret_cast<const uint32_t*>(g_wb + (size_t)cls * DIM);
    float s = 0.0f;
    #pragma unroll
    for (int k = 0; k < 8; ++k) {
        uint32_t fp = s_f[lane + 32 * k];
        uint32_t wp = wr[lane + 32 * k];
        float2 fa = __bfloat1622float2(*reinterpret_cast<__nv_bfloat162*>(&fp));
        float2 wa = __bfloat1622float2(*reinterpret_cast<__nv_bfloat162*>(&wp));
        s = fmaf(fa.x, wa.x, s);
        s = fmaf(fa.y, wa.y, s);
    }
    #pragma unroll
    for (int o = 16; o > 0; o >>= 1) s += __shfl_xor_sync(0xffffffffu, s, o);
    if (lane == 0) sm[warp] = s * 20.0f;
    __syncthreads();
    if (tid == 0) {
        float tgt  = sm[0];
        float auxs = sm[1] + sm[2] + sm[3] + sm[4] + sm[5];
        g_ta[row] = -0.95f * tgt - 0.01f * auxs;
    }
}

// ---------------------------------------------------------------------------
// persistent fused bf16 mma.sync GEMM + fixed-max partial softmax.
// 148 CTAs; unit = (m-tile 128 rows, n-chunk 256 classes); CTA c takes units
// {c, c+148, ...} (static round-robin, 6-7 units each).  Per unit: 8 K64
// stages through the 3-stage cp.async pipeline, then epilogue writes
// (sum, max, idx) partials per (row, warpN-slot) straight to global.
// ---------------------------------------------------------------------------
__global__ void __launch_bounds__(256, 1)
gemm_fused() {
    extern __shared__ char dsm[];
    const int tid   = threadIdx.x;
    const int lane  = tid & 31;
    const int wid   = tid >> 5;
    const int warpM = wid & 1;     // rows warpM*64
    const int warpN = wid >> 1;    // cols warpN*64
    const uint32_t sbase = sm2u(dsm);
    const int cta = blockIdx.x;
    const int myUnits = (NUNITS - cta + GRID - 1) / GRID;   // 7 or 6
    const int S = myUnits * 8;

    // ldmatrix intra-tile offsets
    const uint32_t aoff = (uint32_t)(warpM * 64 + (lane & 15)) * ROWB
                        + (uint32_t)(lane >> 4) * 16;
    const uint32_t boff = (uint32_t)(warpN * 64 + (lane & 7) + ((lane >> 4) << 3)) * ROWB
                        + (uint32_t)((lane >> 3) & 1) * 16;

    float acc[4][8][4];            // [mt][n8][j]
    float vsum[4][2];
    float vmax[4][2];
    int   vidx[4][2];

    // ---- stage loader: A(128x64) + B(256x64), one commit group ----
    auto load_stage = [&](int s, int slot) {
        const int u  = cta + (s >> 3) * GRID;
        const int kb = s & 7;
        const int mtile = u & 127, nch = u >> 7;
        const uint32_t sb = sbase + (uint32_t)slot * STG;
        const __nv_bfloat16* Asrc = g_fb + (size_t)(mtile * TMR) * DIM + kb * BK;
        const __nv_bfloat16* Bsrc = g_wb + (size_t)(nch * NCH) * DIM + kb * BK;
        #pragma unroll
        for (int i = 0; i < 4; ++i) {          // A: 1024 chunks
            int ch = tid + 256 * i;
            int row = ch >> 3, c8 = ch & 7;
            CPASYNC16(sb + (uint32_t)row * ROWB + c8 * 16,
                      Asrc + (size_t)row * DIM + c8 * 8);
        }
        #pragma unroll
        for (int i = 0; i < 8; ++i) {          // B: 2048 chunks
            int ch = tid + 256 * i;
            int row = ch >> 3, c8 = ch & 7;
            CPASYNC16(sb + ABLK + (uint32_t)row * ROWB + c8 * 16,
                      Bsrc + (size_t)row * DIM + c8 * 8);
        }
        asm volatile("cp.async.commit_group;" ::: "memory");
    };

    load_stage(0, 0);
    load_stage(1, 1);

    int csSlot = 0, ldSlot = 2;
    for (int t = 0; t < S; ++t) {
        if (t + 1 < S) {
            asm volatile("cp.async.wait_group 1;" ::: "memory");
        } else {
            asm volatile("cp.async.wait_group 0;" ::: "memory");
        }
        __syncthreads();
        if (t + 2 < S) {
            load_stage(t + 2, ldSlot);
            if (++ldSlot == NSTG) ldSlot = 0;
        }

        if ((t & 7) == 0) {
            #pragma unroll
            for (int mt = 0; mt < 4; ++mt) {
                #pragma unroll
                for (int n8 = 0; n8 < 8; ++n8)
                    #pragma unroll
                    for (int j = 0; j < 4; ++j) acc[mt][n8][j] = 0.0f;
                #pragma unroll
                for (int rh = 0; rh < 2; ++rh) {
                    vsum[mt][rh] = 0.0f; vmax[mt][rh] = -1e30f; vidx[mt][rh] = -1;
                }
            }
        }

        const uint32_t sb = sbase + (uint32_t)csSlot * STG;
        if (++csSlot == NSTG) csSlot = 0;
        const uint32_t aS = sb + aoff;
        const uint32_t bS = sb + ABLK + boff;
        #pragma unroll
        for (int kk = 0; kk < 4; ++kk) {
            uint32_t Af[4][4];
            #pragma unroll
            for (int mt = 0; mt < 4; ++mt)
                LDSM4(Af[mt][0], Af[mt][1], Af[mt][2], Af[mt][3],
                      aS + (uint32_t)mt * 16 * ROWB + kk * 32);
            uint32_t Bf[8][2];
            #pragma unroll
            for (int nt = 0; nt < 4; ++nt) {
                uint32_t r0, r1, r2, r3;
                LDSM4(r0, r1, r2, r3, bS + (uint32_t)nt * 16 * ROWB + kk * 32);
                Bf[2 * nt][0] = r0;     Bf[2 * nt][1] = r1;
                Bf[2 * nt + 1][0] = r2; Bf[2 * nt + 1][1] = r3;
            }
            #pragma unroll
            for (int mt = 0; mt < 4; ++mt)
                #pragma unroll
                for (int n8 = 0; n8 < 8; ++n8)
                    MMA16816(acc[mt][n8], Af[mt], Bf[n8]);
        }

        if ((t & 7) == 7) {
            // unit epilogue: exp(20c - 20), argmax, quad-reduce, global write
            const int u = cta + (t >> 3) * GRID;
            const int mtile = u & 127, nch = u >> 7;
            const int ncBase = nch * NCH + warpN * 64;
            #pragma unroll
            for (int mt = 0; mt < 4; ++mt) {
                #pragma unroll
                for (int n8 = 0; n8 < 8; ++n8) {
                    #pragma unroll
                    for (int j = 0; j < 4; ++j) {
                        int cls = ncBase + n8 * 8 + (lane & 3) * 2 + (j & 1);
                        if (cls < NC) {
                            float v  = acc[mt][n8][j];       // cosine
                            int   rh = j >> 1;
                            if (v > vmax[mt][rh]) { vmax[mt][rh] = v; vidx[mt][rh] = cls; }
                            // exp(20v - 20) = 2^(28.8539*(v-1)); fixed max = 20
                            float tt = fmaf(v, 28.853900817779268f, -28.853900817779268f);
                            float fj = tt + 12582912.0f;      // rn-to-int magic
                            float fi = fj - 12582912.0f;
                            float rr = tt - fi;               // [-0.5, 0.5]
                            int   ei = __float_as_int(fj);
                            int   sb2 = (ei + (127 - 0x4B400000)) << 23;  // 2^n bits
                            float q  = fmaf(rr, 0.0096181291f, 0.055504109f);
                            q = fmaf(rr, q, 0.24022651f);
                            q = fmaf(rr, q, 0.69314718f);
                            q = fmaf(rr, q, 1.0f);
                            vsum[mt][rh] = fmaf(q, __int_as_float(sb2), vsum[mt][rh]);
                        }
                    }
                }
            }
            const int slot = nch * 4 + warpN;
            #pragma unroll
            for (int mt = 0; mt < 4; ++mt) {
                #pragma unroll
                for (int rh = 0; rh < 2; ++rh) {
                    float s = vsum[mt][rh], m = vmax[mt][rh];
                    int   ix = vidx[mt][rh];
                    #pragma unroll
                    for (int o = 1; o <= 2; o <<= 1) {
                        float so = __shfl_xor_sync(0xffffffffu, s, o);
                        float mo = __shfl_xor_sync(0xffffffffu, m, o);
                        int   io = __shfl_xor_sync(0xffffffffu, ix, o);
                        s += so;
                        if (mo > m) { m = mo; ix = io; }
                    }
                    if ((lane & 3) == 0) {
                        int row = mtile * TMR + warpM * 64 + mt * 16 + rh * 8 + (lane >> 2);
                        g_psum[slot * BS + row] = s;
                        g_pmax[slot * BS + row] = m;
                        g_pidx[slot * BS + row] = ix;
                    }
                }
            }
        }
    }
}

// ---------------------------------------------------------------------------
// per-row combine of 32 partial slots -> lse, corr
// ---------------------------------------------------------------------------
__global__ void reduce_kernel(const int* __restrict__ label) {
    int row = blockIdx.x * 256 + threadIdx.x;
    float sum = 0.0f, m = -1e30f;
    int   ix = -1;
    #pragma unroll
    for (int s = 0; s < NSLOT; ++s) {
        sum += g_psum[s * BS + row];
        float mv = g_pmax[s * BS + row];
        if (mv > m) { m = mv; ix = g_pidx[s * BS + row]; }
    }
    g_lse[row]  = 20.0f + __logf(sum);
    g_corr[row] = (ix == label[row]) ? 1.0f : 0.0f;
}

// ---------------------------------------------------------------------------
// final deterministic reduction
// ---------------------------------------------------------------------------
__global__ void final_kernel(float* __restrict__ out, int out_size) {
    int tid = threadIdx.x;
    float sl = 0.0f, sc = 0.0f;
    for (int i = tid; i < BS; i += 1024) {
        sl += g_lse[i] + g_ta[i];
        sc += g_corr[i];
    }
    #pragma unroll
    for (int o = 16; o > 0; o >>= 1) {
        sl += __shfl_xor_sync(0xffffffffu, sl, o);
        sc += __shfl_xor_sync(0xffffffffu, sc, o);
    }
    __shared__ float a1[32], a2[32];
    int w = tid >> 5, l = tid & 31;
    if (l == 0) { a1[w] = sl; a2[w] = sc; }
    __syncthreads();
    if (w == 0) {
        sl = a1[l];
        sc = a2[l];
        #pragma unroll
        for (int o = 16; o > 0; o >>= 1) {
            sl += __shfl_xor_sync(0xffffffffu, sl, o);
            sc += __shfl_xor_sync(0xffffffffu, sc, o);
        }
        if (tid == 0) {
            out[0] = sl * (1.0f / BS);
            if (out_size > 1) out[1] = sc * (1.0f / BS);
        }
    }
}

// ---------------------------------------------------------------------------
// host
// ---------------------------------------------------------------------------
extern "C" void kernel_launch(void* const* d_in, const int* in_sizes, int n_in,
                              void* d_out, int out_size) {
    const float* f     = (const float*)d_in[0];
    const float* w     = (const float*)d_in[1];
    const int*   label = (const int*)d_in[2];
    const int*   aux   = (const int*)d_in[3];
    (void)in_sizes; (void)n_in;

    static int configured = 0;
    if (!configured) {
        cudaFuncSetAttribute(gemm_fused,
                             cudaFuncAttributeMaxDynamicSharedMemorySize, DSMEM);
        configured = 1;
    }

    prep_f_kernel<<<BS / 8, 256>>>(f);
    prep_w_kernel<<<NPADC / 8, 256>>>(w);
    gather_kernel<<<BS, 192>>>(label, aux);
    gemm_fused<<<GRID, 256, DSMEM>>>();
    reduce_kernel<<<BS / 256, 256>>>(label);
    final_kernel<<<1, 1024>>>((float*)d_out, out_size);
}

// round 11
// speedup vs baseline: 2.0630x; 1.0227x over previous
#include <cuda_runtime.h>
#include <cuda_bf16.h>
#include <math.h>
#include <stdint.h>

// ---------------------------------------------------------------------------
// problem constants
// ---------------------------------------------------------------------------
#define BS     16384
#define NC     2000
#define NPADC  2048
#define DIM    512
#define TMR    128              // M rows per tile
#define NCH    256              // classes per N chunk
#define BK     64               // K per stage
#define ROWB   144              // padded smem row stride (72 bf16)
#define ABLK   (128 * ROWB)     // 18432
#define BBLK   (256 * ROWB)     // 36864
#define STG    (ABLK + BBLK)    // 55296
#define NSTG   3
#define DSMEM  (NSTG * STG)     // 165888
#define GRID   148              // persistent CTAs (one per SM)
#define NUNITS 1024             // 128 m-tiles * 8 n-chunks
#define NSLOT  32               // 8 n-chunks * 4 warpN partials per row

// ---------------------------------------------------------------------------
// device scratch (allocation-free)
// ---------------------------------------------------------------------------
__device__ float g_ta[BS];
__device__ float g_lse[BS];
__device__ float g_corr[BS];
__device__ float g_psum[NSLOT * BS];    // [slot][row] partial exp-sums
__device__ float g_pmax[NSLOT * BS];    // [slot][row] partial maxima
__device__ int   g_pidx[NSLOT * BS];    // [slot][row] partial argmax
__device__ __nv_bfloat16 g_fb[(size_t)BS * DIM];
__device__ __nv_bfloat16 g_wb[(size_t)NPADC * DIM];

// ---------------------------------------------------------------------------
// helpers
// ---------------------------------------------------------------------------
static __device__ __forceinline__ uint32_t sm2u(const void* p) {
    uint32_t a;
    asm("{ .reg .u64 t; cvta.to.shared.u64 t, %1; cvt.u32.u64 %0, t; }"
        : "=r"(a) : "l"(p));
    return a;
}

#define LDSM4(r0, r1, r2, r3, addr) \
    asm volatile("ldmatrix.sync.aligned.m8n8.x4.shared.b16 {%0,%1,%2,%3}, [%4];" \
                 : "=r"(r0), "=r"(r1), "=r"(r2), "=r"(r3) : "r"(addr))

#define MMA16816(d, a, b) \
    asm volatile("mma.sync.aligned.m16n8k16.row.col.f32.bf16.bf16.f32 " \
                 "{%0,%1,%2,%3}, {%4,%5,%6,%7}, {%8,%9}, {%0,%1,%2,%3};" \
                 : "+f"((d)[0]), "+f"((d)[1]), "+f"((d)[2]), "+f"((d)[3]) \
                 : "r"((a)[0]), "r"((a)[1]), "r"((a)[2]), "r"((a)[3]), \
                   "r"((b)[0]), "r"((b)[1]))

#define CPASYNC16(dst, src) \
    asm volatile("cp.async.cg.shared.global [%0], [%1], 16;" :: "r"(dst), "l"(src))

// ---------------------------------------------------------------------------
// prep: warp-per-row rownorm + bf16 convert; f and w in one launch.
// blocks [0, BS/8)           -> f rows
// blocks [BS/8, BS/8+NPADC/8) -> w rows (zero-pad past NC)
// ---------------------------------------------------------------------------
__global__ void prep_kernel(const float* __restrict__ f, const float* __restrict__ w) {
    int warp = threadIdx.x >> 5;
    int lane = threadIdx.x & 31;
    int b    = blockIdx.x;

    const float* x;
    __nv_bfloat16* out;
    int row;
    if (b < BS / 8) {
        row = b * 8 + warp;
        x = f + (size_t)row * DIM;
        out = g_fb + (size_t)row * DIM;
    } else {
        row = (b - BS / 8) * 8 + warp;
        out = g_wb + (size_t)row * DIM;
        if (row >= NC) {
            uint2 z; z.x = 0u; z.y = 0u;
            uint2* dp = reinterpret_cast<uint2*>(out);
            #pragma unroll
            for (int k = 0; k < 4; ++k) dp[lane + 32 * k] = z;
            return;
        }
        x = w + (size_t)row * DIM;
    }

    const float4* p = reinterpret_cast<const float4*>(x);
    float4 v[4];
    float s = 0.0f;
    #pragma unroll
    for (int k = 0; k < 4; ++k) {
        v[k] = p[lane + 32 * k];
        s += v[k].x * v[k].x + v[k].y * v[k].y + v[k].z * v[k].z + v[k].w * v[k].w;
    }
    #pragma unroll
    for (int o = 16; o > 0; o >>= 1) s += __shfl_xor_sync(0xffffffffu, s, o);
    float inv = 1.0f / fmaxf(sqrtf(s), 1e-12f);
    uint2* dp = reinterpret_cast<uint2*>(out);
    #pragma unroll
    for (int k = 0; k < 4; ++k) {
        __nv_bfloat162 h0 = __floats2bfloat162_rn(v[k].x * inv, v[k].y * inv);
        __nv_bfloat162 h1 = __floats2bfloat162_rn(v[k].z * inv, v[k].w * inv);
        uint2 u;
        u.x = *reinterpret_cast<uint32_t*>(&h0);
        u.y = *reinterpret_cast<uint32_t*>(&h1);
        dp[lane + 32 * k] = u;
    }
}

// ---------------------------------------------------------------------------
// persistent fused bf16 mma.sync GEMM + fixed-max partial softmax
// + distributed tgt/aux gather (16 rows per unit, 2 per warp).
// 148 CTAs; unit = (m-tile 128 rows, n-chunk 256 classes); CTA c takes units
// {c, c+148, ...}.  Per unit: 8 K64 stages through the 3-stage cp.async
// pipeline, epilogue writes (sum, max, idx) partials to global, then the
// unit's gather rows are handled from L2-resident g_fb/g_wb.
// ---------------------------------------------------------------------------
__global__ void __launch_bounds__(256, 1)
gemm_fused(const int* __restrict__ label, const int* __restrict__ aux) {
    extern __shared__ char dsm[];
    const int tid   = threadIdx.x;
    const int lane  = tid & 31;
    const int wid   = tid >> 5;
    const int warpM = wid & 1;     // rows warpM*64
    const int warpN = wid >> 1;    // cols warpN*64
    const uint32_t sbase = sm2u(dsm);
    const int cta = blockIdx.x;
    const int myUnits = (NUNITS - cta + GRID - 1) / GRID;   // 7 or 6
    const int S = myUnits * 8;

    // ldmatrix intra-tile offsets
    const uint32_t aoff = (uint32_t)(warpM * 64 + (lane & 15)) * ROWB
                        + (uint32_t)(lane >> 4) * 16;
    const uint32_t boff = (uint32_t)(warpN * 64 + (lane & 7) + ((lane >> 4) << 3)) * ROWB
                        + (uint32_t)((lane >> 3) & 1) * 16;

    float acc[4][8][4];            // [mt][n8][j]
    float vsum[4][2];
    float vmax[4][2];
    int   vidx[4][2];

    // ---- stage loader: A(128x64) + B(256x64), one commit group ----
    auto load_stage = [&](int s, int slot) {
        const int u  = cta + (s >> 3) * GRID;
        const int kb = s & 7;
        const int mtile = u & 127, nch = u >> 7;
        const uint32_t sb = sbase + (uint32_t)slot * STG;
        const __nv_bfloat16* Asrc = g_fb + (size_t)(mtile * TMR) * DIM + kb * BK;
        const __nv_bfloat16* Bsrc = g_wb + (size_t)(nch * NCH) * DIM + kb * BK;
        #pragma unroll
        for (int i = 0; i < 4; ++i) {          // A: 1024 chunks
            int ch = tid + 256 * i;
            int row = ch >> 3, c8 = ch & 7;
            CPASYNC16(sb + (uint32_t)row * ROWB + c8 * 16,
                      Asrc + (size_t)row * DIM + c8 * 8);
        }
        #pragma unroll
        for (int i = 0; i < 8; ++i) {          // B: 2048 chunks
            int ch = tid + 256 * i;
            int row = ch >> 3, c8 = ch & 7;
            CPASYNC16(sb + ABLK + (uint32_t)row * ROWB + c8 * 16,
                      Bsrc + (size_t)row * DIM + c8 * 8);
        }
        asm volatile("cp.async.commit_group;" ::: "memory");
    };

    load_stage(0, 0);
    load_stage(1, 1);

    int csSlot = 0, ldSlot = 2;
    for (int t = 0; t < S; ++t) {
        if (t + 1 < S) {
            asm volatile("cp.async.wait_group 1;" ::: "memory");
        } else {
            asm volatile("cp.async.wait_group 0;" ::: "memory");
        }
        __syncthreads();
        if (t + 2 < S) {
            load_stage(t + 2, ldSlot);
            if (++ldSlot == NSTG) ldSlot = 0;
        }

        if ((t & 7) == 0) {
            #pragma unroll
            for (int mt = 0; mt < 4; ++mt) {
                #pragma unroll
                for (int n8 = 0; n8 < 8; ++n8)
                    #pragma unroll
                    for (int j = 0; j < 4; ++j) acc[mt][n8][j] = 0.0f;
                #pragma unroll
                for (int rh = 0; rh < 2; ++rh) {
                    vsum[mt][rh] = 0.0f; vmax[mt][rh] = -1e30f; vidx[mt][rh] = -1;
                }
            }
        }

        const uint32_t sb = sbase + (uint32_t)csSlot * STG;
        if (++csSlot == NSTG) csSlot = 0;
        const uint32_t aS = sb + aoff;
        const uint32_t bS = sb + ABLK + boff;
        #pragma unroll
        for (int kk = 0; kk < 4; ++kk) {
            uint32_t Af[4][4];
            #pragma unroll
            for (int mt = 0; mt < 4; ++mt)
                LDSM4(Af[mt][0], Af[mt][1], Af[mt][2], Af[mt][3],
                      aS + (uint32_t)mt * 16 * ROWB + kk * 32);
            uint32_t Bf[8][2];
            #pragma unroll
            for (int nt = 0; nt < 4; ++nt) {
                uint32_t r0, r1, r2, r3;
                LDSM4(r0, r1, r2, r3, bS + (uint32_t)nt * 16 * ROWB + kk * 32);
                Bf[2 * nt][0] = r0;     Bf[2 * nt][1] = r1;
                Bf[2 * nt + 1][0] = r2; Bf[2 * nt + 1][1] = r3;
            }
            #pragma unroll
            for (int mt = 0; mt < 4; ++mt)
                #pragma unroll
                for (int n8 = 0; n8 < 8; ++n8)
                    MMA16816(acc[mt][n8], Af[mt], Bf[n8]);
        }

        if ((t & 7) == 7) {
            // unit epilogue: exp(20c - 20), argmax, quad-reduce, global write
            const int u = cta + (t >> 3) * GRID;
            const int mtile = u & 127, nch = u >> 7;
            const int ncBase = nch * NCH + warpN * 64;
            #pragma unroll
            for (int mt = 0; mt < 4; ++mt) {
                #pragma unroll
                for (int n8 = 0; n8 < 8; ++n8) {
                    #pragma unroll
                    for (int j = 0; j < 4; ++j) {
                        int cls = ncBase + n8 * 8 + (lane & 3) * 2 + (j & 1);
                        if (cls < NC) {
                            float v  = acc[mt][n8][j];       // cosine
                            int   rh = j >> 1;
                            if (v > vmax[mt][rh]) { vmax[mt][rh] = v; vidx[mt][rh] = cls; }
                            // exp(20v - 20) = 2^(28.8539*(v-1)); fixed max = 20
                            float tt = fmaf(v, 28.853900817779268f, -28.853900817779268f);
                            float fj = tt + 12582912.0f;      // rn-to-int magic
                            float fi = fj - 12582912.0f;
                            float rr = tt - fi;               // [-0.5, 0.5]
                            int   ei = __float_as_int(fj);
                            int   sb2 = (ei + (127 - 0x4B400000)) << 23;  // 2^n bits
                            float q  = fmaf(rr, 0.0096181291f, 0.055504109f);
                            q = fmaf(rr, q, 0.24022651f);
                            q = fmaf(rr, q, 0.69314718f);
                            q = fmaf(rr, q, 1.0f);
                            vsum[mt][rh] = fmaf(q, __int_as_float(sb2), vsum[mt][rh]);
                        }
                    }
                }
            }
            const int slot = nch * 4 + warpN;
            #pragma unroll
            for (int mt = 0; mt < 4; ++mt) {
                #pragma unroll
                for (int rh = 0; rh < 2; ++rh) {
                    float s = vsum[mt][rh], m = vmax[mt][rh];
                    int   ix = vidx[mt][rh];
                    #pragma unroll
                    for (int o = 1; o <= 2; o <<= 1) {
                        float so = __shfl_xor_sync(0xffffffffu, s, o);
                        float mo = __shfl_xor_sync(0xffffffffu, m, o);
                        int   io = __shfl_xor_sync(0xffffffffu, ix, o);
                        s += so;
                        if (mo > m) { m = mo; ix = io; }
                    }
                    if ((lane & 3) == 0) {
                        int row = mtile * TMR + warpM * 64 + mt * 16 + rh * 8 + (lane >> 2);
                        g_psum[slot * BS + row] = s;
                        g_pmax[slot * BS + row] = m;
                        g_pidx[slot * BS + row] = ix;
                    }
                }
            }

            // ---- distributed gather: rows [u*16, u*16+16), 2 per warp ----
            {
                const int grow0 = u * 16 + wid * 2;
                #pragma unroll
                for (int r = 0; r < 2; ++r) {
                    const int row = grow0 + r;
                    const uint32_t* fr = reinterpret_cast<const uint32_t*>(
                        g_fb + (size_t)row * DIM);
                    uint32_t ff[8];
                    #pragma unroll
                    for (int k = 0; k < 8; ++k) ff[k] = fr[lane + 32 * k];
                    float acc6[6];
                    #pragma unroll
                    for (int c = 0; c < 6; ++c) {
                        int cls = (c == 0) ? label[row] : aux[row * 5 + c - 1];
                        const uint32_t* wr2 = reinterpret_cast<const uint32_t*>(
                            g_wb + (size_t)cls * DIM);
                        float s = 0.0f;
                        #pragma unroll
                        for (int k = 0; k < 8; ++k) {
                            uint32_t wp = wr2[lane + 32 * k];
                            float2 fa = __bfloat1622float2(
                                *reinterpret_cast<__nv_bfloat162*>(&ff[k]));
                            float2 wa = __bfloat1622float2(
                                *reinterpret_cast<__nv_bfloat162*>(&wp));
                            s = fmaf(fa.x, wa.x, s);
                            s = fmaf(fa.y, wa.y, s);
                        }
                        #pragma unroll
                        for (int o = 16; o > 0; o >>= 1)
                            s += __shfl_xor_sync(0xffffffffu, s, o);
                        acc6[c] = s;
                    }
                    if (lane == 0) {
                        float tgt  = acc6[0] * 20.0f;
                        float auxs = (acc6[1] + acc6[2] + acc6[3]
                                    + acc6[4] + acc6[5]) * 20.0f;
                        g_ta[row] = -0.95f * tgt - 0.01f * auxs;
                    }
                }
            }
        }
    }
}

// ---------------------------------------------------------------------------
// per-row combine of 32 partial slots -> lse, corr
// ---------------------------------------------------------------------------
__global__ void reduce_kernel(const int* __restrict__ label) {
    int row = blockIdx.x * 256 + threadIdx.x;
    float sum = 0.0f, m = -1e30f;
    int   ix = -1;
    #pragma unroll
    for (int s = 0; s < NSLOT; ++s) {
        sum += g_psum[s * BS + row];
        float mv = g_pmax[s * BS + row];
        if (mv > m) { m = mv; ix = g_pidx[s * BS + row]; }
    }
    g_lse[row]  = 20.0f + __logf(sum);
    g_corr[row] = (ix == label[row]) ? 1.0f : 0.0f;
}

// ---------------------------------------------------------------------------
// final deterministic reduction
// ---------------------------------------------------------------------------
__global__ void final_kernel(float* __restrict__ out, int out_size) {
    int tid = threadIdx.x;
    float sl = 0.0f, sc = 0.0f;
    for (int i = tid; i < BS; i += 1024) {
        sl += g_lse[i] + g_ta[i];
        sc += g_corr[i];
    }
    #pragma unroll
    for (int o = 16; o > 0; o >>= 1) {
        sl += __shfl_xor_sync(0xffffffffu, sl, o);
        sc += __shfl_xor_sync(0xffffffffu, sc, o);
    }
    __shared__ float a1[32], a2[32];
    int w = tid >> 5, l = tid & 31;
    if (l == 0) { a1[w] = sl; a2[w] = sc; }
    __syncthreads();
    if (w == 0) {
        sl = a1[l];
        sc = a2[l];
        #pragma unroll
        for (int o = 16; o > 0; o >>= 1) {
            sl += __shfl_xor_sync(0xffffffffu, sl, o);
            sc += __shfl_xor_sync(0xffffffffu, sc, o);
        }
        if (tid == 0) {
            out[0] = sl * (1.0f / BS);
            if (out_size > 1) out[1] = sc * (1.0f / BS);
        }
    }
}

// ---------------------------------------------------------------------------
// host
// ---------------------------------------------------------------------------
extern "C" void kernel_launch(void* const* d_in, const int* in_sizes, int n_in,
                              void* d_out, int out_size) {
    const float* f     = (const float*)d_in[0];
    const float* w     = (const float*)d_in[1];
    const int*   label = (const int*)d_in[2];
    const int*   aux   = (const int*)d_in[3];
    (void)in_sizes; (void)n_in;

    static int configured = 0;
    if (!configured) {
        cudaFuncSetAttribute(gemm_fused,
                             cudaFuncAttributeMaxDynamicSharedMemorySize, DSMEM);
        configured = 1;
    }

    prep_kernel<<<BS / 8 + NPADC / 8, 256>>>(f, w);
    gemm_fused<<<GRID, 256, DSMEM>>>(label, aux);
    reduce_kernel<<<BS / 256, 256>>>(label);
    final_kernel<<<1, 1024>>>((float*)d_out, out_size);
}

// round 12
// speedup vs baseline: 2.1377x; 1.0362x over previous
#include <cuda_runtime.h>
#include <cuda_bf16.h>
#include <math.h>
#include <stdint.h>

// ---------------------------------------------------------------------------
// problem constants
// ---------------------------------------------------------------------------
#define BS     16384
#define NC     2000
#define NPADC  2048
#define DIM    512
#define TMR    128              // M rows per tile
#define NCH    256              // classes per N chunk
#define BK     64               // K per stage
#define ROWB   144              // padded smem row stride (72 bf16)
#define ABLK   (128 * ROWB)     // 18432
#define BBLK   (256 * ROWB)     // 36864
#define STG    (ABLK + BBLK)    // 55296
#define NSTG   3
#define DSMEM  (NSTG * STG)     // 165888
#define GRID   148              // persistent CTAs (one per SM)
#define NUNITS 1024             // 128 m-tiles * 8 n-chunks
#define NSLOT  32               // 8 n-chunks * 4 warpN partials per row
#define NRB    64               // reduce blocks

// ---------------------------------------------------------------------------
// device scratch (allocation-free)
// ---------------------------------------------------------------------------
__device__ float g_ta[BS];
__device__ float g_psum[NSLOT * BS];    // [slot][row] partial exp-sums
__device__ float g_pmax[NSLOT * BS];    // [slot][row] partial maxima
__device__ int   g_pidx[NSLOT * BS];    // [slot][row] partial argmax
__device__ float g_blkl[NRB];           // per-block loss partials
__device__ float g_blkc[NRB];           // per-block acc partials
__device__ __nv_bfloat16 g_fb[(size_t)BS * DIM];
__device__ __nv_bfloat16 g_wb[(size_t)NPADC * DIM];

// ---------------------------------------------------------------------------
// helpers
// ---------------------------------------------------------------------------
static __device__ __forceinline__ uint32_t sm2u(const void* p) {
    uint32_t a;
    asm("{ .reg .u64 t; cvta.to.shared.u64 t, %1; cvt.u32.u64 %0, t; }"
        : "=r"(a) : "l"(p));
    return a;
}

#define LDSM4(r0, r1, r2, r3, addr) \
    asm volatile("ldmatrix.sync.aligned.m8n8.x4.shared.b16 {%0,%1,%2,%3}, [%4];" \
                 : "=r"(r0), "=r"(r1), "=r"(r2), "=r"(r3) : "r"(addr))

#define MMA16816(d, a, b) \
    asm volatile("mma.sync.aligned.m16n8k16.row.col.f32.bf16.bf16.f32 " \
                 "{%0,%1,%2,%3}, {%4,%5,%6,%7}, {%8,%9}, {%0,%1,%2,%3};" \
                 : "+f"((d)[0]), "+f"((d)[1]), "+f"((d)[2]), "+f"((d)[3]) \
                 : "r"((a)[0]), "r"((a)[1]), "r"((a)[2]), "r"((a)[3]), \
                   "r"((b)[0]), "r"((b)[1]))

#define CPASYNC16(dst, src) \
    asm volatile("cp.async.cg.shared.global [%0], [%1], 16;" :: "r"(dst), "l"(src))

// ---------------------------------------------------------------------------
// prep: warp-per-row rownorm + bf16 convert; f and w in one launch.
// ---------------------------------------------------------------------------
__global__ void prep_kernel(const float* __restrict__ f, const float* __restrict__ w) {
    int warp = threadIdx.x >> 5;
    int lane = threadIdx.x & 31;
    int b    = blockIdx.x;

    const float* x;
    __nv_bfloat16* out;
    int row;
    if (b < BS / 8) {
        row = b * 8 + warp;
        x = f + (size_t)row * DIM;
        out = g_fb + (size_t)row * DIM;
    } else {
        row = (b - BS / 8) * 8 + warp;
        out = g_wb + (size_t)row * DIM;
        if (row >= NC) {
            uint2 z; z.x = 0u; z.y = 0u;
            uint2* dp = reinterpret_cast<uint2*>(out);
            #pragma unroll
            for (int k = 0; k < 4; ++k) dp[lane + 32 * k] = z;
            return;
        }
        x = w + (size_t)row * DIM;
    }

    const float4* p = reinterpret_cast<const float4*>(x);
    float4 v[4];
    float s = 0.0f;
    #pragma unroll
    for (int k = 0; k < 4; ++k) {
        v[k] = p[lane + 32 * k];
        s += v[k].x * v[k].x + v[k].y * v[k].y + v[k].z * v[k].z + v[k].w * v[k].w;
    }
    #pragma unroll
    for (int o = 16; o > 0; o >>= 1) s += __shfl_xor_sync(0xffffffffu, s, o);
    float inv = 1.0f / fmaxf(sqrtf(s), 1e-12f);
    uint2* dp = reinterpret_cast<uint2*>(out);
    #pragma unroll
    for (int k = 0; k < 4; ++k) {
        __nv_bfloat162 h0 = __floats2bfloat162_rn(v[k].x * inv, v[k].y * inv);
        __nv_bfloat162 h1 = __floats2bfloat162_rn(v[k].z * inv, v[k].w * inv);
        uint2 u;
        u.x = *reinterpret_cast<uint32_t*>(&h0);
        u.y = *reinterpret_cast<uint32_t*>(&h1);
        dp[lane + 32 * k] = u;
    }
}

// ---------------------------------------------------------------------------
// persistent fused bf16 mma.sync GEMM + fixed-max partial softmax
// + distributed tgt/aux gather (16 rows per unit, 2 per warp).
// ---------------------------------------------------------------------------
__global__ void __launch_bounds__(256, 1)
gemm_fused(const int* __restrict__ label, const int* __restrict__ aux) {
    extern __shared__ char dsm[];
    const int tid   = threadIdx.x;
    const int lane  = tid & 31;
    const int wid   = tid >> 5;
    const int warpM = wid & 1;     // rows warpM*64
    const int warpN = wid >> 1;    // cols warpN*64
    const uint32_t sbase = sm2u(dsm);
    const int cta = blockIdx.x;
    const int myUnits = (NUNITS - cta + GRID - 1) / GRID;   // 7 or 6
    const int S = myUnits * 8;

    // ldmatrix intra-tile offsets
    const uint32_t aoff = (uint32_t)(warpM * 64 + (lane & 15)) * ROWB
                        + (uint32_t)(lane >> 4) * 16;
    const uint32_t boff = (uint32_t)(warpN * 64 + (lane & 7) + ((lane >> 4) << 3)) * ROWB
                        + (uint32_t)((lane >> 3) & 1) * 16;

    float acc[4][8][4];            // [mt][n8][j]
    float vsum[4][2];
    float vmax[4][2];
    int   vidx[4][2];

    // ---- stage loader: A(128x64) + B(256x64), one commit group ----
    auto load_stage = [&](int s, int slot) {
        const int u  = cta + (s >> 3) * GRID;
        const int kb = s & 7;
        const int mtile = u & 127, nch = u >> 7;
        const uint32_t sb = sbase + (uint32_t)slot * STG;
        const __nv_bfloat16* Asrc = g_fb + (size_t)(mtile * TMR) * DIM + kb * BK;
        const __nv_bfloat16* Bsrc = g_wb + (size_t)(nch * NCH) * DIM + kb * BK;
        #pragma unroll
        for (int i = 0; i < 4; ++i) {          // A: 1024 chunks
            int ch = tid + 256 * i;
            int row = ch >> 3, c8 = ch & 7;
            CPASYNC16(sb + (uint32_t)row * ROWB + c8 * 16,
                      Asrc + (size_t)row * DIM + c8 * 8);
        }
        #pragma unroll
        for (int i = 0; i < 8; ++i) {          // B: 2048 chunks
            int ch = tid + 256 * i;
            int row = ch >> 3, c8 = ch & 7;
            CPASYNC16(sb + ABLK + (uint32_t)row * ROWB + c8 * 16,
                      Bsrc + (size_t)row * DIM + c8 * 8);
        }
        asm volatile("cp.async.commit_group;" ::: "memory");
    };

    load_stage(0, 0);
    load_stage(1, 1);

    int csSlot = 0, ldSlot = 2;
    for (int t = 0; t < S; ++t) {
        if (t + 1 < S) {
            asm volatile("cp.async.wait_group 1;" ::: "memory");
        } else {
            asm volatile("cp.async.wait_group 0;" ::: "memory");
        }
        __syncthreads();
        if (t + 2 < S) {
            load_stage(t + 2, ldSlot);
            if (++ldSlot == NSTG) ldSlot = 0;
        }

        if ((t & 7) == 0) {
            #pragma unroll
            for (int mt = 0; mt < 4; ++mt) {
                #pragma unroll
                for (int n8 = 0; n8 < 8; ++n8)
                    #pragma unroll
                    for (int j = 0; j < 4; ++j) acc[mt][n8][j] = 0.0f;
                #pragma unroll
                for (int rh = 0; rh < 2; ++rh) {
                    vsum[mt][rh] = 0.0f; vmax[mt][rh] = -1e30f; vidx[mt][rh] = -1;
                }
            }
        }

        const uint32_t sb = sbase + (uint32_t)csSlot * STG;
        if (++csSlot == NSTG) csSlot = 0;
        const uint32_t aS = sb + aoff;
        const uint32_t bS = sb + ABLK + boff;
        #pragma unroll
        for (int kk = 0; kk < 4; ++kk) {
            uint32_t Af[4][4];
            #pragma unroll
            for (int mt = 0; mt < 4; ++mt)
                LDSM4(Af[mt][0], Af[mt][1], Af[mt][2], Af[mt][3],
                      aS + (uint32_t)mt * 16 * ROWB + kk * 32);
            uint32_t Bf[8][2];
            #pragma unroll
            for (int nt = 0; nt < 4; ++nt) {
                uint32_t r0, r1, r2, r3;
                LDSM4(r0, r1, r2, r3, bS + (uint32_t)nt * 16 * ROWB + kk * 32);
                Bf[2 * nt][0] = r0;     Bf[2 * nt][1] = r1;
                Bf[2 * nt + 1][0] = r2; Bf[2 * nt + 1][1] = r3;
            }
            #pragma unroll
            for (int mt = 0; mt < 4; ++mt)
                #pragma unroll
                for (int n8 = 0; n8 < 8; ++n8)
                    MMA16816(acc[mt][n8], Af[mt], Bf[n8]);
        }

        if ((t & 7) == 7) {
            // unit epilogue: exp(20c - 20), argmax, quad-reduce, global write
            const int u = cta + (t >> 3) * GRID;
            const int mtile = u & 127, nch = u >> 7;
            const int ncBase = nch * NCH + warpN * 64;
            #pragma unroll
            for (int mt = 0; mt < 4; ++mt) {
                #pragma unroll
                for (int n8 = 0; n8 < 8; ++n8) {
                    #pragma unroll
                    for (int j = 0; j < 4; ++j) {
                        int cls = ncBase + n8 * 8 + (lane & 3) * 2 + (j & 1);
                        if (cls < NC) {
                            float v  = acc[mt][n8][j];       // cosine
                            int   rh = j >> 1;
                            if (v > vmax[mt][rh]) { vmax[mt][rh] = v; vidx[mt][rh] = cls; }
                            // exp(20v - 20) = 2^(28.8539*(v-1)); fixed max = 20
                            float tt = fmaf(v, 28.853900817779268f, -28.853900817779268f);
                            float fj = tt + 12582912.0f;      // rn-to-int magic
                            float fi = fj - 12582912.0f;
                            float rr = tt - fi;               // [-0.5, 0.5]
                            int   ei = __float_as_int(fj);
                            int   sb2 = (ei + (127 - 0x4B400000)) << 23;  // 2^n bits
                            float q  = fmaf(rr, 0.0096181291f, 0.055504109f);
                            q = fmaf(rr, q, 0.24022651f);
                            q = fmaf(rr, q, 0.69314718f);
                            q = fmaf(rr, q, 1.0f);
                            vsum[mt][rh] = fmaf(q, __int_as_float(sb2), vsum[mt][rh]);
                        }
                    }
                }
            }
            const int slot = nch * 4 + warpN;
            #pragma unroll
            for (int mt = 0; mt < 4; ++mt) {
                #pragma unroll
                for (int rh = 0; rh < 2; ++rh) {
                    float s = vsum[mt][rh], m = vmax[mt][rh];
                    int   ix = vidx[mt][rh];
                    #pragma unroll
                    for (int o = 1; o <= 2; o <<= 1) {
                        float so = __shfl_xor_sync(0xffffffffu, s, o);
                        float mo = __shfl_xor_sync(0xffffffffu, m, o);
                        int   io = __shfl_xor_sync(0xffffffffu, ix, o);
                        s += so;
                        if (mo > m) { m = mo; ix = io; }
                    }
                    if ((lane & 3) == 0) {
                        int row = mtile * TMR + warpM * 64 + mt * 16 + rh * 8 + (lane >> 2);
                        g_psum[slot * BS + row] = s;
                        g_pmax[slot * BS + row] = m;
                        g_pidx[slot * BS + row] = ix;
                    }
                }
            }

            // ---- distributed gather: rows [u*16, u*16+16), 2 per warp ----
            {
                const int grow0 = u * 16 + wid * 2;
                #pragma unroll
                for (int r = 0; r < 2; ++r) {
                    const int row = grow0 + r;
                    const uint32_t* fr = reinterpret_cast<const uint32_t*>(
                        g_fb + (size_t)row * DIM);
                    uint32_t ff[8];
                    #pragma unroll
                    for (int k = 0; k < 8; ++k) ff[k] = fr[lane + 32 * k];
                    float acc6[6];
                    #pragma unroll
                    for (int c = 0; c < 6; ++c) {
                        int cls = (c == 0) ? label[row] : aux[row * 5 + c - 1];
                        const uint32_t* wr2 = reinterpret_cast<const uint32_t*>(
                            g_wb + (size_t)cls * DIM);
                        float s = 0.0f;
                        #pragma unroll
                        for (int k = 0; k < 8; ++k) {
                            uint32_t wp = wr2[lane + 32 * k];
                            float2 fa = __bfloat1622float2(
                                *reinterpret_cast<__nv_bfloat162*>(&ff[k]));
                            float2 wa = __bfloat1622float2(
                                *reinterpret_cast<__nv_bfloat162*>(&wp));
                            s = fmaf(fa.x, wa.x, s);
                            s = fmaf(fa.y, wa.y, s);
                        }
                        #pragma unroll
                        for (int o = 16; o > 0; o >>= 1)
                            s += __shfl_xor_sync(0xffffffffu, s, o);
                        acc6[c] = s;
                    }
                    if (lane == 0) {
                        float tgt  = acc6[0] * 20.0f;
                        float auxs = (acc6[1] + acc6[2] + acc6[3]
                                    + acc6[4] + acc6[5]) * 20.0f;
                        g_ta[row] = -0.95f * tgt - 0.01f * auxs;
                    }
                }
            }
        }
    }
}

// ---------------------------------------------------------------------------
// per-row combine of 32 partial slots -> per-block (loss, acc) partials
// ---------------------------------------------------------------------------
__global__ void reduce_kernel(const int* __restrict__ label) {
    int tid = threadIdx.x;
    int row = blockIdx.x * 256 + tid;
    float sum = 0.0f, m = -1e30f;
    int   ix = -1;
    #pragma unroll
    for (int s = 0; s < NSLOT; ++s) {
        sum += g_psum[s * BS + row];
        float mv = g_pmax[s * BS + row];
        if (mv > m) { m = mv; ix = g_pidx[s * BS + row]; }
    }
    float sl = 20.0f + __logf(sum) + g_ta[row];
    float sc = (ix == label[row]) ? 1.0f : 0.0f;

    // deterministic block reduction of (sl, sc)
    #pragma unroll
    for (int o = 16; o > 0; o >>= 1) {
        sl += __shfl_xor_sync(0xffffffffu, sl, o);
        sc += __shfl_xor_sync(0xffffffffu, sc, o);
    }
    __shared__ float a1[8], a2[8];
    int w = tid >> 5, l = tid & 31;
    if (l == 0) { a1[w] = sl; a2[w] = sc; }
    __syncthreads();
    if (tid == 0) {
        float t1 = 0.0f, t2 = 0.0f;
        #pragma unroll
        for (int k = 0; k < 8; ++k) { t1 += a1[k]; t2 += a2[k]; }
        g_blkl[blockIdx.x] = t1;
        g_blkc[blockIdx.x] = t2;
    }
}

// ---------------------------------------------------------------------------
// final: sum 64 block partials -> loss, acc
// ---------------------------------------------------------------------------
__global__ void final_kernel(float* __restrict__ out, int out_size) {
    int tid = threadIdx.x;          // 64 threads
    float sl = g_blkl[tid];
    float sc = g_blkc[tid];
    #pragma unroll
    for (int o = 16; o > 0; o >>= 1) {
        sl += __shfl_xor_sync(0xffffffffu, sl, o);
        sc += __shfl_xor_sync(0xffffffffu, sc, o);
    }
    __shared__ float a1[2], a2[2];
    if ((tid & 31) == 0) { a1[tid >> 5] = sl; a2[tid >> 5] = sc; }
    __syncthreads();
    if (tid == 0) {
        out[0] = (a1[0] + a1[1]) * (1.0f / BS);
        if (out_size > 1) out[1] = (a2[0] + a2[1]) * (1.0f / BS);
    }
}

// ---------------------------------------------------------------------------
// host
// ---------------------------------------------------------------------------
extern "C" void kernel_launch(void* const* d_in, const int* in_sizes, int n_in,
                              void* d_out, int out_size) {
    const float* f     = (const float*)d_in[0];
    const float* w     = (const float*)d_in[1];
    const int*   label = (const int*)d_in[2];
    const int*   aux   = (const int*)d_in[3];
    (void)in_sizes; (void)n_in;

    static int configured = 0;
    if (!configured) {
        cudaFuncSetAttribute(gemm_fused,
                             cudaFuncAttributeMaxDynamicSharedMemorySize, DSMEM);
        configured = 1;
    }

    prep_kernel<<<BS / 8 + NPADC / 8, 256>>>(f, w);
    gemm_fused<<<GRID, 256, DSMEM>>>(label, aux);
    reduce_kernel<<<NRB, 256>>>(label);
    final_kernel<<<1, 64>>>((float*)d_out, out_size);
}

// round 13
// speedup vs baseline: 2.1566x; 1.0088x over previous
#include <cuda_runtime.h>
#include <cuda_bf16.h>
#include <math.h>
#include <stdint.h>

// ---------------------------------------------------------------------------
// problem constants
// ---------------------------------------------------------------------------
#define BS     16384
#define NC     2000
#define NPADC  2048
#define DIM    512
#define TMR    128              // M rows per tile
#define NCH    256              // classes per N chunk
#define BK     64               // K per stage
#define ROWB   144              // padded smem row stride (72 bf16)
#define ABLK   (128 * ROWB)     // 18432
#define BBLK   (256 * ROWB)     // 36864
#define STG    (ABLK + BBLK)    // 55296
#define NSTG   3
#define DSMEM  (NSTG * STG)     // 165888
#define GRID   148              // persistent CTAs (one per SM)
#define NUNITS 1024             // 128 m-tiles * 8 n-chunks
#define NSLOT  8                // 8 n-chunk partials per row (warpN pre-combined)
#define NRB    64               // reduce blocks

// ---------------------------------------------------------------------------
// device scratch (allocation-free)
// ---------------------------------------------------------------------------
__device__ float g_ta[BS];
__device__ float g_psum[NSLOT * BS];    // [slot][row] partial exp-sums
__device__ float g_pmax[NSLOT * BS];    // [slot][row] partial maxima
__device__ int   g_pidx[NSLOT * BS];    // [slot][row] partial argmax
__device__ float g_blkl[NRB];           // per-block loss partials
__device__ float g_blkc[NRB];           // per-block acc partials
__device__ unsigned int g_ctr;          // reduce completion counter (zero-init)
__device__ __nv_bfloat16 g_fb[(size_t)BS * DIM];
__device__ __nv_bfloat16 g_wb[(size_t)NPADC * DIM];

// ---------------------------------------------------------------------------
// helpers
// ---------------------------------------------------------------------------
static __device__ __forceinline__ uint32_t sm2u(const void* p) {
    uint32_t a;
    asm("{ .reg .u64 t; cvta.to.shared.u64 t, %1; cvt.u32.u64 %0, t; }"
        : "=r"(a) : "l"(p));
    return a;
}

#define LDSM4(r0, r1, r2, r3, addr) \
    asm volatile("ldmatrix.sync.aligned.m8n8.x4.shared.b16 {%0,%1,%2,%3}, [%4];" \
                 : "=r"(r0), "=r"(r1), "=r"(r2), "=r"(r3) : "r"(addr))

#define MMA16816(d, a, b) \
    asm volatile("mma.sync.aligned.m16n8k16.row.col.f32.bf16.bf16.f32 " \
                 "{%0,%1,%2,%3}, {%4,%5,%6,%7}, {%8,%9}, {%0,%1,%2,%3};" \
                 : "+f"((d)[0]), "+f"((d)[1]), "+f"((d)[2]), "+f"((d)[3]) \
                 : "r"((a)[0]), "r"((a)[1]), "r"((a)[2]), "r"((a)[3]), \
                   "r"((b)[0]), "r"((b)[1]))

#define CPASYNC16(dst, src) \
    asm volatile("cp.async.cg.shared.global [%0], [%1], 16;" :: "r"(dst), "l"(src))

// ---------------------------------------------------------------------------
// prep: warp-per-row rownorm + bf16 convert; f and w in one launch.
// ---------------------------------------------------------------------------
__global__ void prep_kernel(const float* __restrict__ f, const float* __restrict__ w) {
    int warp = threadIdx.x >> 5;
    int lane = threadIdx.x & 31;
    int b    = blockIdx.x;

    const float* x;
    __nv_bfloat16* out;
    int row;
    if (b < BS / 8) {
        row = b * 8 + warp;
        x = f + (size_t)row * DIM;
        out = g_fb + (size_t)row * DIM;
    } else {
        row = (b - BS / 8) * 8 + warp;
        out = g_wb + (size_t)row * DIM;
        if (row >= NC) {
            uint2 z; z.x = 0u; z.y = 0u;
            uint2* dp = reinterpret_cast<uint2*>(out);
            #pragma unroll
            for (int k = 0; k < 4; ++k) dp[lane + 32 * k] = z;
            return;
        }
        x = w + (size_t)row * DIM;
    }

    const float4* p = reinterpret_cast<const float4*>(x);
    float4 v[4];
    float s = 0.0f;
    #pragma unroll
    for (int k = 0; k < 4; ++k) {
        v[k] = p[lane + 32 * k];
        s += v[k].x * v[k].x + v[k].y * v[k].y + v[k].z * v[k].z + v[k].w * v[k].w;
    }
    #pragma unroll
    for (int o = 16; o > 0; o >>= 1) s += __shfl_xor_sync(0xffffffffu, s, o);
    float inv = 1.0f / fmaxf(sqrtf(s), 1e-12f);
    uint2* dp = reinterpret_cast<uint2*>(out);
    #pragma unroll
    for (int k = 0; k < 4; ++k) {
        __nv_bfloat162 h0 = __floats2bfloat162_rn(v[k].x * inv, v[k].y * inv);
        __nv_bfloat162 h1 = __floats2bfloat162_rn(v[k].z * inv, v[k].w * inv);
        uint2 u;
        u.x = *reinterpret_cast<uint32_t*>(&h0);
        u.y = *reinterpret_cast<uint32_t*>(&h1);
        dp[lane + 32 * k] = u;
    }
}

// ---------------------------------------------------------------------------
// persistent fused bf16 mma.sync GEMM + fixed-max partial softmax
// + distributed tgt/aux gather (16 rows per unit, 2 per warp).
// warpN partials combined in smem -> 1 slot per (row, n-chunk).
// ---------------------------------------------------------------------------
__global__ void __launch_bounds__(256, 1)
gemm_fused(const int* __restrict__ label, const int* __restrict__ aux) {
    extern __shared__ char dsm[];
    __shared__ float sredS[4][TMR];
    __shared__ float sredM[4][TMR];
    __shared__ int   sredI[4][TMR];

    const int tid   = threadIdx.x;
    const int lane  = tid & 31;
    const int wid   = tid >> 5;
    const int warpM = wid & 1;     // rows warpM*64
    const int warpN = wid >> 1;    // cols warpN*64
    const uint32_t sbase = sm2u(dsm);
    const int cta = blockIdx.x;
    const int myUnits = (NUNITS - cta + GRID - 1) / GRID;   // 7 or 6
    const int S = myUnits * 8;

    // ldmatrix intra-tile offsets
    const uint32_t aoff = (uint32_t)(warpM * 64 + (lane & 15)) * ROWB
                        + (uint32_t)(lane >> 4) * 16;
    const uint32_t boff = (uint32_t)(warpN * 64 + (lane & 7) + ((lane >> 4) << 3)) * ROWB
                        + (uint32_t)((lane >> 3) & 1) * 16;

    float acc[4][8][4];            // [mt][n8][j]
    float vsum[4][2];
    float vmax[4][2];
    int   vidx[4][2];

    // ---- stage loader: A(128x64) + B(256x64), one commit group ----
    auto load_stage = [&](int s, int slot) {
        const int u  = cta + (s >> 3) * GRID;
        const int kb = s & 7;
        const int mtile = u & 127, nch = u >> 7;
        const uint32_t sb = sbase + (uint32_t)slot * STG;
        const __nv_bfloat16* Asrc = g_fb + (size_t)(mtile * TMR) * DIM + kb * BK;
        const __nv_bfloat16* Bsrc = g_wb + (size_t)(nch * NCH) * DIM + kb * BK;
        #pragma unroll
        for (int i = 0; i < 4; ++i) {          // A: 1024 chunks
            int ch = tid + 256 * i;
            int row = ch >> 3, c8 = ch & 7;
            CPASYNC16(sb + (uint32_t)row * ROWB + c8 * 16,
                      Asrc + (size_t)row * DIM + c8 * 8);
        }
        #pragma unroll
        for (int i = 0; i < 8; ++i) {          // B: 2048 chunks
            int ch = tid + 256 * i;
            int row = ch >> 3, c8 = ch & 7;
            CPASYNC16(sb + ABLK + (uint32_t)row * ROWB + c8 * 16,
                      Bsrc + (size_t)row * DIM + c8 * 8);
        }
        asm volatile("cp.async.commit_group;" ::: "memory");
    };

    load_stage(0, 0);
    load_stage(1, 1);

    int csSlot = 0, ldSlot = 2;
    for (int t = 0; t < S; ++t) {
        if (t + 1 < S) {
            asm volatile("cp.async.wait_group 1;" ::: "memory");
        } else {
            asm volatile("cp.async.wait_group 0;" ::: "memory");
        }
        __syncthreads();
        if (t + 2 < S) {
            load_stage(t + 2, ldSlot);
            if (++ldSlot == NSTG) ldSlot = 0;
        }

        if ((t & 7) == 0) {
            #pragma unroll
            for (int mt = 0; mt < 4; ++mt) {
                #pragma unroll
                for (int n8 = 0; n8 < 8; ++n8)
                    #pragma unroll
                    for (int j = 0; j < 4; ++j) acc[mt][n8][j] = 0.0f;
                #pragma unroll
                for (int rh = 0; rh < 2; ++rh) {
                    vsum[mt][rh] = 0.0f; vmax[mt][rh] = -1e30f; vidx[mt][rh] = -1;
                }
            }
        }

        const uint32_t sb = sbase + (uint32_t)csSlot * STG;
        if (++csSlot == NSTG) csSlot = 0;
        const uint32_t aS = sb + aoff;
        const uint32_t bS = sb + ABLK + boff;
        #pragma unroll
        for (int kk = 0; kk < 4; ++kk) {
            uint32_t Af[4][4];
            #pragma unroll
            for (int mt = 0; mt < 4; ++mt)
                LDSM4(Af[mt][0], Af[mt][1], Af[mt][2], Af[mt][3],
                      aS + (uint32_t)mt * 16 * ROWB + kk * 32);
            uint32_t Bf[8][2];
            #pragma unroll
            for (int nt = 0; nt < 4; ++nt) {
                uint32_t r0, r1, r2, r3;
                LDSM4(r0, r1, r2, r3, bS + (uint32_t)nt * 16 * ROWB + kk * 32);
                Bf[2 * nt][0] = r0;     Bf[2 * nt][1] = r1;
                Bf[2 * nt + 1][0] = r2; Bf[2 * nt + 1][1] = r3;
            }
            #pragma unroll
            for (int mt = 0; mt < 4; ++mt)
                #pragma unroll
                for (int n8 = 0; n8 < 8; ++n8)
                    MMA16816(acc[mt][n8], Af[mt], Bf[n8]);
        }

        if ((t & 7) == 7) {
            // unit epilogue: exp(20c - 20), argmax, quad-reduce,
            // warpN combine via smem, single global write per row.
            const int u = cta + (t >> 3) * GRID;
            const int mtile = u & 127, nch = u >> 7;
            const int ncBase = nch * NCH + warpN * 64;
            #pragma unroll
            for (int mt = 0; mt < 4; ++mt) {
                #pragma unroll
                for (int n8 = 0; n8 < 8; ++n8) {
                    #pragma unroll
                    for (int j = 0; j < 4; ++j) {
                        int cls = ncBase + n8 * 8 + (lane & 3) * 2 + (j & 1);
                        if (cls < NC) {
                            float v  = acc[mt][n8][j];       // cosine
                            int   rh = j >> 1;
                            if (v > vmax[mt][rh]) { vmax[mt][rh] = v; vidx[mt][rh] = cls; }
                            // exp(20v - 20) = 2^(28.8539*(v-1)); fixed max = 20
                            float tt = fmaf(v, 28.853900817779268f, -28.853900817779268f);
                            float fj = tt + 12582912.0f;      // rn-to-int magic
                            float fi = fj - 12582912.0f;
                            float rr = tt - fi;               // [-0.5, 0.5]
                            int   ei = __float_as_int(fj);
                            int   sb2 = (ei + (127 - 0x4B400000)) << 23;  // 2^n bits
                            float q  = fmaf(rr, 0.0096181291f, 0.055504109f);
                            q = fmaf(rr, q, 0.24022651f);
                            q = fmaf(rr, q, 0.69314718f);
                            q = fmaf(rr, q, 1.0f);
                            vsum[mt][rh] = fmaf(q, __int_as_float(sb2), vsum[mt][rh]);
                        }
                    }
                }
            }
            #pragma unroll
            for (int mt = 0; mt < 4; ++mt) {
                #pragma unroll
                for (int rh = 0; rh < 2; ++rh) {
                    float s = vsum[mt][rh], m = vmax[mt][rh];
                    int   ix = vidx[mt][rh];
                    #pragma unroll
                    for (int o = 1; o <= 2; o <<= 1) {
                        float so = __shfl_xor_sync(0xffffffffu, s, o);
                        float mo = __shfl_xor_sync(0xffffffffu, m, o);
                        int   io = __shfl_xor_sync(0xffffffffu, ix, o);
                        s += so;
                        if (mo > m) { m = mo; ix = io; }
                    }
                    if ((lane & 3) == 0) {
                        int r = warpM * 64 + mt * 16 + rh * 8 + (lane >> 2);
                        sredS[warpN][r] = s;
                        sredM[warpN][r] = m;
                        sredI[warpN][r] = ix;
                    }
                }
            }
            __syncthreads();
            if (tid < TMR) {
                float s = sredS[0][tid], m = sredM[0][tid];
                int   ix = sredI[0][tid];
                #pragma unroll
                for (int wn = 1; wn < 4; ++wn) {
                    s += sredS[wn][tid];
                    float mw = sredM[wn][tid];
                    if (mw > m) { m = mw; ix = sredI[wn][tid]; }
                }
                int row = mtile * TMR + tid;
                g_psum[nch * BS + row] = s;
                g_pmax[nch * BS + row] = m;
                g_pidx[nch * BS + row] = ix;
            }

            // ---- distributed gather: rows [u*16, u*16+16), 2 per warp ----
            {
                const int grow0 = u * 16 + wid * 2;
                #pragma unroll
                for (int r = 0; r < 2; ++r) {
                    const int row = grow0 + r;
                    const uint32_t* fr = reinterpret_cast<const uint32_t*>(
                        g_fb + (size_t)row * DIM);
                    uint32_t ff[8];
                    #pragma unroll
                    for (int k = 0; k < 8; ++k) ff[k] = fr[lane + 32 * k];
                    float acc6[6];
                    #pragma unroll
                    for (int c = 0; c < 6; ++c) {
                        int cls = (c == 0) ? label[row] : aux[row * 5 + c - 1];
                        const uint32_t* wr2 = reinterpret_cast<const uint32_t*>(
                            g_wb + (size_t)cls * DIM);
                        float s = 0.0f;
                        #pragma unroll
                        for (int k = 0; k < 8; ++k) {
                            uint32_t wp = wr2[lane + 32 * k];
                            float2 fa = __bfloat1622float2(
                                *reinterpret_cast<__nv_bfloat162*>(&ff[k]));
                            float2 wa = __bfloat1622float2(
                                *reinterpret_cast<__nv_bfloat162*>(&wp));
                            s = fmaf(fa.x, wa.x, s);
                            s = fmaf(fa.y, wa.y, s);
                        }
                        #pragma unroll
                        for (int o = 16; o > 0; o >>= 1)
                            s += __shfl_xor_sync(0xffffffffu, s, o);
                        acc6[c] = s;
                    }
                    if (lane == 0) {
                        float tgt  = acc6[0] * 20.0f;
                        float auxs = (acc6[1] + acc6[2] + acc6[3]
                                    + acc6[4] + acc6[5]) * 20.0f;
                        g_ta[row] = -0.95f * tgt - 0.01f * auxs;
                    }
                }
            }
        }
    }
}

// ---------------------------------------------------------------------------
// per-row combine of 8 slots -> per-block partials; last block sums them.
// ---------------------------------------------------------------------------
__global__ void reduce_kernel(const int* __restrict__ label,
                              float* __restrict__ out, int out_size) {
    int tid = threadIdx.x;
    int row = blockIdx.x * 256 + tid;
    float sum = 0.0f, m = -1e30f;
    int   ix = -1;
    #pragma unroll
    for (int s = 0; s < NSLOT; ++s) {
        sum += g_psum[s * BS + row];
        float mv = g_pmax[s * BS + row];
        if (mv > m) { m = mv; ix = g_pidx[s * BS + row]; }
    }
    float sl = 20.0f + __logf(sum) + g_ta[row];
    float sc = (ix == label[row]) ? 1.0f : 0.0f;

    // deterministic block reduction of (sl, sc)
    #pragma unroll
    for (int o = 16; o > 0; o >>= 1) {
        sl += __shfl_xor_sync(0xffffffffu, sl, o);
        sc += __shfl_xor_sync(0xffffffffu, sc, o);
    }
    __shared__ float a1[8], a2[8];
    __shared__ bool isLast;
    int w = tid >> 5, l = tid & 31;
    if (l == 0) { a1[w] = sl; a2[w] = sc; }
    __syncthreads();
    if (tid == 0) {
        float t1 = 0.0f, t2 = 0.0f;
        #pragma unroll
        for (int k = 0; k < 8; ++k) { t1 += a1[k]; t2 += a2[k]; }
        g_blkl[blockIdx.x] = t1;
        g_blkc[blockIdx.x] = t2;
        __threadfence();
        unsigned int r = atomicAdd(&g_ctr, 1u);
        isLast = (r == NRB - 1);
    }
    __syncthreads();

    // last-arriving block performs the (deterministic, fixed-order) final sum
    if (isLast && tid < NRB) {
        float fl = g_blkl[tid];
        float fc = g_blkc[tid];
        #pragma unroll
        for (int o = 16; o > 0; o >>= 1) {
            fl += __shfl_xor_sync(0xffffffffu, fl, o);
            fc += __shfl_xor_sync(0xffffffffu, fc, o);
        }
        if (l == 0) { a1[w] = fl; a2[w] = fc; }
        __syncwarp(0xffffffffu);
        if (tid == 0) {
            // wait for warp1's write: tid 0..63 spans 2 warps -> combine via smem
        }
    }
    if (isLast) __syncthreads();
    if (isLast && tid == 0) {
        out[0] = (a1[0] + a1[1]) * (1.0f / BS);
        if (out_size > 1) out[1] = (a2[0] + a2[1]) * (1.0f / BS);
        g_ctr = 0;                 // reset for graph replay
    }
}

// ---------------------------------------------------------------------------
// host
// ---------------------------------------------------------------------------
extern "C" void kernel_launch(void* const* d_in, const int* in_sizes, int n_in,
                              void* d_out, int out_size) {
    const float* f     = (const float*)d_in[0];
    const float* w     = (const float*)d_in[1];
    const int*   label = (const int*)d_in[2];
    const int*   aux   = (const int*)d_in[3];
    (void)in_sizes; (void)n_in;

    static int configured = 0;
    if (!configured) {
        cudaFuncSetAttribute(gemm_fused,
                             cudaFuncAttributeMaxDynamicSharedMemorySize, DSMEM);
        configured = 1;
    }

    prep_kernel<<<BS / 8 + NPADC / 8, 256>>>(f, w);
    gemm_fused<<<GRID, 256, DSMEM>>>(label, aux);
    reduce_kernel<<<NRB, 256>>>(label, (float*)d_out, out_size);
}

// round 14
// speedup vs baseline: 2.3744x; 1.1010x over previous
#include <cuda_runtime.h>
#include <cuda_bf16.h>
#include <math.h>
#include <stdint.h>

// ---------------------------------------------------------------------------
// problem constants
// ---------------------------------------------------------------------------
#define BS     16384
#define NC     2000
#define NPADC  2048
#define DIM    512
#define TMR    128              // M rows per tile
#define NCH    256              // classes per N chunk
#define BK     64               // K per stage
#define ROWB   144              // padded smem row stride (72 bf16)
#define ABLK   (128 * ROWB)     // 18432
#define BBLK   (256 * ROWB)     // 36864
#define STG    (ABLK + BBLK)    // 55296
#define NSTG   3
#define DSMEM  (NSTG * STG)     // 165888
#define GRID   148              // persistent CTAs (one per SM)
#define NUNITS 1024             // 128 m-tiles * 8 n-chunks
#define NSLOT  8                // 8 n-chunk partials per row (warpN pre-combined)
#define NRB    64               // reduce blocks
#define K20    28.853900817779268f   // 20 / ln(2)

// ---------------------------------------------------------------------------
// device scratch (allocation-free)
// ---------------------------------------------------------------------------
__device__ float g_ta[BS];
__device__ float g_psum[NSLOT * BS];    // [slot][row] partial exp-sums
__device__ float g_pmax[NSLOT * BS];    // [slot][row] partial maxima
__device__ int   g_pidx[NSLOT * BS];    // [slot][row] partial argmax
__device__ float g_blkl[NRB];           // per-block loss partials
__device__ float g_blkc[NRB];           // per-block acc partials
__device__ unsigned int g_ctr;          // reduce completion counter (zero-init)
__device__ __nv_bfloat16 g_fb[(size_t)BS * DIM];
__device__ __nv_bfloat16 g_wb[(size_t)NPADC * DIM];

// ---------------------------------------------------------------------------
// helpers
// ---------------------------------------------------------------------------
static __device__ __forceinline__ uint32_t sm2u(const void* p) {
    uint32_t a;
    asm("{ .reg .u64 t; cvta.to.shared.u64 t, %1; cvt.u32.u64 %0, t; }"
        : "=r"(a) : "l"(p));
    return a;
}

static __device__ __forceinline__ float ex2f(float x) {
    float y;
    asm("ex2.approx.f32 %0, %1;" : "=f"(y) : "f"(x));
    return y;
}

#define LDSM4(r0, r1, r2, r3, addr) \
    asm volatile("ldmatrix.sync.aligned.m8n8.x4.shared.b16 {%0,%1,%2,%3}, [%4];" \
                 : "=r"(r0), "=r"(r1), "=r"(r2), "=r"(r3) : "r"(addr))

#define MMA16816(d, a, b) \
    asm volatile("mma.sync.aligned.m16n8k16.row.col.f32.bf16.bf16.f32 " \
                 "{%0,%1,%2,%3}, {%4,%5,%6,%7}, {%8,%9}, {%0,%1,%2,%3};" \
                 : "+f"((d)[0]), "+f"((d)[1]), "+f"((d)[2]), "+f"((d)[3]) \
                 : "r"((a)[0]), "r"((a)[1]), "r"((a)[2]), "r"((a)[3]), \
                   "r"((b)[0]), "r"((b)[1]))

#define CPASYNC16(dst, src) \
    asm volatile("cp.async.cg.shared.global [%0], [%1], 16;" :: "r"(dst), "l"(src))

// ---------------------------------------------------------------------------
// prep: warp-per-row rownorm + bf16 convert; f and w in one launch.
// ---------------------------------------------------------------------------
__global__ void prep_kernel(const float* __restrict__ f, const float* __restrict__ w) {
    int warp = threadIdx.x >> 5;
    int lane = threadIdx.x & 31;
    int b    = blockIdx.x;

    const float* x;
    __nv_bfloat16* out;
    int row;
    if (b < BS / 8) {
        row = b * 8 + warp;
        x = f + (size_t)row * DIM;
        out = g_fb + (size_t)row * DIM;
    } else {
        row = (b - BS / 8) * 8 + warp;
        out = g_wb + (size_t)row * DIM;
        if (row >= NC) {
            uint2 z; z.x = 0u; z.y = 0u;
            uint2* dp = reinterpret_cast<uint2*>(out);
            #pragma unroll
            for (int k = 0; k < 4; ++k) dp[lane + 32 * k] = z;
            return;
        }
        x = w + (size_t)row * DIM;
    }

    const float4* p = reinterpret_cast<const float4*>(x);
    float4 v[4];
    float s = 0.0f;
    #pragma unroll
    for (int k = 0; k < 4; ++k) {
        v[k] = p[lane + 32 * k];
        s += v[k].x * v[k].x + v[k].y * v[k].y + v[k].z * v[k].z + v[k].w * v[k].w;
    }
    #pragma unroll
    for (int o = 16; o > 0; o >>= 1) s += __shfl_xor_sync(0xffffffffu, s, o);
    float inv = 1.0f / fmaxf(sqrtf(s), 1e-12f);
    uint2* dp = reinterpret_cast<uint2*>(out);
    #pragma unroll
    for (int k = 0; k < 4; ++k) {
        __nv_bfloat162 h0 = __floats2bfloat162_rn(v[k].x * inv, v[k].y * inv);
        __nv_bfloat162 h1 = __floats2bfloat162_rn(v[k].z * inv, v[k].w * inv);
        uint2 u;
        u.x = *reinterpret_cast<uint32_t*>(&h0);
        u.y = *reinterpret_cast<uint32_t*>(&h1);
        dp[lane + 32 * k] = u;
    }
}

// ---------------------------------------------------------------------------
// persistent fused bf16 mma.sync GEMM + fixed-max partial softmax (MUFU exp)
// + distributed tgt/aux gather (16 rows per unit, 2 per warp).
// ---------------------------------------------------------------------------
__global__ void __launch_bounds__(256, 1)
gemm_fused(const int* __restrict__ label, const int* __restrict__ aux) {
    extern __shared__ char dsm[];
    __shared__ float sredS[4][TMR];
    __shared__ float sredM[4][TMR];
    __shared__ int   sredI[4][TMR];

    const int tid   = threadIdx.x;
    const int lane  = tid & 31;
    const int wid   = tid >> 5;
    const int warpM = wid & 1;     // rows warpM*64
    const int warpN = wid >> 1;    // cols warpN*64
    const uint32_t sbase = sm2u(dsm);
    const int cta = blockIdx.x;
    const int myUnits = (NUNITS - cta + GRID - 1) / GRID;   // 7 or 6
    const int S = myUnits * 8;

    // ldmatrix intra-tile offsets
    const uint32_t aoff = (uint32_t)(warpM * 64 + (lane & 15)) * ROWB
                        + (uint32_t)(lane >> 4) * 16;
    const uint32_t boff = (uint32_t)(warpN * 64 + (lane & 7) + ((lane >> 4) << 3)) * ROWB
                        + (uint32_t)((lane >> 3) & 1) * 16;

    float acc[4][8][4];            // [mt][n8][j]
    float vsum[4][2];
    float vmax[4][2];
    int   vidx[4][2];

    // ---- stage loader: A(128x64) + B(256x64), one commit group ----
    auto load_stage = [&](int s, int slot) {
        const int u  = cta + (s >> 3) * GRID;
        const int kb = s & 7;
        const int mtile = u & 127, nch = u >> 7;
        const uint32_t sb = sbase + (uint32_t)slot * STG;
        const __nv_bfloat16* Asrc = g_fb + (size_t)(mtile * TMR) * DIM + kb * BK;
        const __nv_bfloat16* Bsrc = g_wb + (size_t)(nch * NCH) * DIM + kb * BK;
        #pragma unroll
        for (int i = 0; i < 4; ++i) {          // A: 1024 chunks
            int ch = tid + 256 * i;
            int row = ch >> 3, c8 = ch & 7;
            CPASYNC16(sb + (uint32_t)row * ROWB + c8 * 16,
                      Asrc + (size_t)row * DIM + c8 * 8);
        }
        #pragma unroll
        for (int i = 0; i < 8; ++i) {          // B: 2048 chunks
            int ch = tid + 256 * i;
            int row = ch >> 3, c8 = ch & 7;
            CPASYNC16(sb + ABLK + (uint32_t)row * ROWB + c8 * 16,
                      Bsrc + (size_t)row * DIM + c8 * 8);
        }
        asm volatile("cp.async.commit_group;" ::: "memory");
    };

    load_stage(0, 0);
    load_stage(1, 1);

    int csSlot = 0, ldSlot = 2;
    for (int t = 0; t < S; ++t) {
        if (t + 1 < S) {
            asm volatile("cp.async.wait_group 1;" ::: "memory");
        } else {
            asm volatile("cp.async.wait_group 0;" ::: "memory");
        }
        __syncthreads();
        if (t + 2 < S) {
            load_stage(t + 2, ldSlot);
            if (++ldSlot == NSTG) ldSlot = 0;
        }

        if ((t & 7) == 0) {
            #pragma unroll
            for (int mt = 0; mt < 4; ++mt) {
                #pragma unroll
                for (int n8 = 0; n8 < 8; ++n8)
                    #pragma unroll
                    for (int j = 0; j < 4; ++j) acc[mt][n8][j] = 0.0f;
                #pragma unroll
                for (int rh = 0; rh < 2; ++rh) {
                    vsum[mt][rh] = 0.0f; vmax[mt][rh] = -1e30f; vidx[mt][rh] = -1;
                }
            }
        }

        const uint32_t sb = sbase + (uint32_t)csSlot * STG;
        if (++csSlot == NSTG) csSlot = 0;
        const uint32_t aS = sb + aoff;
        const uint32_t bS = sb + ABLK + boff;
        #pragma unroll
        for (int kk = 0; kk < 4; ++kk) {
            uint32_t Af[4][4];
            #pragma unroll
            for (int mt = 0; mt < 4; ++mt)
                LDSM4(Af[mt][0], Af[mt][1], Af[mt][2], Af[mt][3],
                      aS + (uint32_t)mt * 16 * ROWB + kk * 32);
            uint32_t Bf[8][2];
            #pragma unroll
            for (int nt = 0; nt < 4; ++nt) {
                uint32_t r0, r1, r2, r3;
                LDSM4(r0, r1, r2, r3, bS + (uint32_t)nt * 16 * ROWB + kk * 32);
                Bf[2 * nt][0] = r0;     Bf[2 * nt][1] = r1;
                Bf[2 * nt + 1][0] = r2; Bf[2 * nt + 1][1] = r3;
            }
            #pragma unroll
            for (int mt = 0; mt < 4; ++mt)
                #pragma unroll
                for (int n8 = 0; n8 < 8; ++n8)
                    MMA16816(acc[mt][n8], Af[mt], Bf[n8]);
        }

        if ((t & 7) == 7) {
            // unit epilogue: exp via MUFU ex2, argmax, quad-reduce,
            // warpN combine via smem, single global write per row.
            const int u = cta + (t >> 3) * GRID;
            const int mtile = u & 127, nch = u >> 7;
            const int ncBase = nch * NCH + warpN * 64;
            if (ncBase + 64 <= NC) {
                // fast path: no padding in this warp's 64 columns
                #pragma unroll
                for (int mt = 0; mt < 4; ++mt) {
                    #pragma unroll
                    for (int n8 = 0; n8 < 8; ++n8) {
                        #pragma unroll
                        for (int j = 0; j < 4; ++j) {
                            int cls = ncBase + n8 * 8 + (lane & 3) * 2 + (j & 1);
                            float v  = acc[mt][n8][j];
                            int   rh = j >> 1;
                            if (v > vmax[mt][rh]) { vmax[mt][rh] = v; vidx[mt][rh] = cls; }
                            vsum[mt][rh] += ex2f(fmaf(v, K20, -K20));
                        }
                    }
                }
            } else {
                #pragma unroll
                for (int mt = 0; mt < 4; ++mt) {
                    #pragma unroll
                    for (int n8 = 0; n8 < 8; ++n8) {
                        #pragma unroll
                        for (int j = 0; j < 4; ++j) {
                            int cls = ncBase + n8 * 8 + (lane & 3) * 2 + (j & 1);
                            if (cls < NC) {
                                float v  = acc[mt][n8][j];
                                int   rh = j >> 1;
                                if (v > vmax[mt][rh]) { vmax[mt][rh] = v; vidx[mt][rh] = cls; }
                                vsum[mt][rh] += ex2f(fmaf(v, K20, -K20));
                            }
                        }
                    }
                }
            }
            #pragma unroll
            for (int mt = 0; mt < 4; ++mt) {
                #pragma unroll
                for (int rh = 0; rh < 2; ++rh) {
                    float s = vsum[mt][rh], m = vmax[mt][rh];
                    int   ix = vidx[mt][rh];
                    #pragma unroll
                    for (int o = 1; o <= 2; o <<= 1) {
                        float so = __shfl_xor_sync(0xffffffffu, s, o);
                        float mo = __shfl_xor_sync(0xffffffffu, m, o);
                        int   io = __shfl_xor_sync(0xffffffffu, ix, o);
                        s += so;
                        if (mo > m) { m = mo; ix = io; }
                    }
                    if ((lane & 3) == 0) {
                        int r = warpM * 64 + mt * 16 + rh * 8 + (lane >> 2);
                        sredS[warpN][r] = s;
                        sredM[warpN][r] = m;
                        sredI[warpN][r] = ix;
                    }
                }
            }
            __syncthreads();
            if (tid < TMR) {
                float s = sredS[0][tid], m = sredM[0][tid];
                int   ix = sredI[0][tid];
                #pragma unroll
                for (int wn = 1; wn < 4; ++wn) {
                    s += sredS[wn][tid];
                    float mw = sredM[wn][tid];
                    if (mw > m) { m = mw; ix = sredI[wn][tid]; }
                }
                int row = mtile * TMR + tid;
                g_psum[nch * BS + row] = s;
                g_pmax[nch * BS + row] = m;
                g_pidx[nch * BS + row] = ix;
            }

            // ---- distributed gather: rows [u*16, u*16+16), 2 per warp ----
            {
                const int grow0 = u * 16 + wid * 2;
                #pragma unroll
                for (int r = 0; r < 2; ++r) {
                    const int row = grow0 + r;
                    const uint32_t* fr = reinterpret_cast<const uint32_t*>(
                        g_fb + (size_t)row * DIM);
                    uint32_t ff[8];
                    #pragma unroll
                    for (int k = 0; k < 8; ++k) ff[k] = fr[lane + 32 * k];
                    float acc6[6];
                    #pragma unroll
                    for (int c = 0; c < 6; ++c) {
                        int cls = (c == 0) ? label[row] : aux[row * 5 + c - 1];
                        const uint32_t* wr2 = reinterpret_cast<const uint32_t*>(
                            g_wb + (size_t)cls * DIM);
                        float s = 0.0f;
                        #pragma unroll
                        for (int k = 0; k < 8; ++k) {
                            uint32_t wp = wr2[lane + 32 * k];
                            float2 fa = __bfloat1622float2(
                                *reinterpret_cast<__nv_bfloat162*>(&ff[k]));
                            float2 wa = __bfloat1622float2(
                                *reinterpret_cast<__nv_bfloat162*>(&wp));
                            s = fmaf(fa.x, wa.x, s);
                            s = fmaf(fa.y, wa.y, s);
                        }
                        #pragma unroll
                        for (int o = 16; o > 0; o >>= 1)
                            s += __shfl_xor_sync(0xffffffffu, s, o);
                        acc6[c] = s;
                    }
                    if (lane == 0) {
                        float tgt  = acc6[0] * 20.0f;
                        float auxs = (acc6[1] + acc6[2] + acc6[3]
                                    + acc6[4] + acc6[5]) * 20.0f;
                        g_ta[row] = -0.95f * tgt - 0.01f * auxs;
                    }
                }
            }
        }
    }
}

// ---------------------------------------------------------------------------
// per-row combine of 8 slots -> per-block partials; last block sums them.
// ---------------------------------------------------------------------------
__global__ void reduce_kernel(const int* __restrict__ label,
                              float* __restrict__ out, int out_size) {
    int tid = threadIdx.x;
    int row = blockIdx.x * 256 + tid;
    float sum = 0.0f, m = -1e30f;
    int   ix = -1;
    #pragma unroll
    for (int s = 0; s < NSLOT; ++s) {
        sum += g_psum[s * BS + row];
        float mv = g_pmax[s * BS + row];
        if (mv > m) { m = mv; ix = g_pidx[s * BS + row]; }
    }
    float sl = 20.0f + __logf(sum) + g_ta[row];
    float sc = (ix == label[row]) ? 1.0f : 0.0f;

    // deterministic block reduction of (sl, sc)
    #pragma unroll
    for (int o = 16; o > 0; o >>= 1) {
        sl += __shfl_xor_sync(0xffffffffu, sl, o);
        sc += __shfl_xor_sync(0xffffffffu, sc, o);
    }
    __shared__ float a1[8], a2[8];
    __shared__ bool isLast;
    int w = tid >> 5, l = tid & 31;
    if (l == 0) { a1[w] = sl; a2[w] = sc; }
    __syncthreads();
    if (tid == 0) {
        float t1 = 0.0f, t2 = 0.0f;
        #pragma unroll
        for (int k = 0; k < 8; ++k) { t1 += a1[k]; t2 += a2[k]; }
        g_blkl[blockIdx.x] = t1;
        g_blkc[blockIdx.x] = t2;
        __threadfence();
        unsigned int r = atomicAdd(&g_ctr, 1u);
        isLast = (r == NRB - 1);
    }
    __syncthreads();

    // last-arriving block performs the (deterministic, fixed-order) final sum
    if (isLast && tid < NRB) {
        float fl = g_blkl[tid];
        float fc = g_blkc[tid];
        #pragma unroll
        for (int o = 16; o > 0; o >>= 1) {
            fl += __shfl_xor_sync(0xffffffffu, fl, o);
            fc += __shfl_xor_sync(0xffffffffu, fc, o);
        }
        if (l == 0) { a1[w] = fl; a2[w] = fc; }
    }
    if (isLast) __syncthreads();
    if (isLast && tid == 0) {
        out[0] = (a1[0] + a1[1]) * (1.0f / BS);
        if (out_size > 1) out[1] = (a2[0] + a2[1]) * (1.0f / BS);
        g_ctr = 0;                 // reset for graph replay
    }
}

// ---------------------------------------------------------------------------
// host
// ---------------------------------------------------------------------------
extern "C" void kernel_launch(void* const* d_in, const int* in_sizes, int n_in,
                              void* d_out, int out_size) {
    const float* f     = (const float*)d_in[0];
    const float* w     = (const float*)d_in[1];
    const int*   label = (const int*)d_in[2];
    const int*   aux   = (const int*)d_in[3];
    (void)in_sizes; (void)n_in;

    static int configured = 0;
    if (!configured) {
        cudaFuncSetAttribute(gemm_fused,
                             cudaFuncAttributeMaxDynamicSharedMemorySize, DSMEM);
        configured = 1;
    }

    prep_kernel<<<BS / 8 + NPADC / 8, 256>>>(f, w);
    gemm_fused<<<GRID, 256, DSMEM>>>(label, aux);
    reduce_kernel<<<NRB, 256>>>(label, (float*)d_out, out_size);
}